// round 1
// baseline (speedup 1.0000x reference)
#include <cuda_runtime.h>
#include <cstdint>

#define NN 20000
#define EE 640000
#define FF 32
#define HH 4
#define CC 64
#define SS 6
#define BB 16
#define DD 64
#define HC 256   // H*C

// ---------------- device scratch (allocation-free rule: __device__ globals) ----------------
__device__ int    g_counts[NN];
__device__ int    g_rowptr[NN + 1];
__device__ int    g_wpos[NN];
__device__ int    g_col[EE];
__device__ int    g_batchcnt[BB];
__device__ float  g_h1[(size_t)NN * HC];     // x @ W1            20.48 MB
__device__ float  g_out1[(size_t)NN * HC];   // relu(gat1 out)    20.48 MB
__device__ float4 g_ssrc1[NN];
__device__ float4 g_sdst1[NN];
__device__ float  g_h2[(size_t)NN * CC];     // out1 @ W2          5.12 MB
__device__ float  g_ssrc2[NN];
__device__ float  g_sdst2[NN];
__device__ float4 g_alpha[EE];               // per-edge exp scores (gat2 reuses as float)
__device__ float  g_pooled[BB * SS * DD];
__device__ float  g_qkv[96 * 192];
__device__ float  g_go[96 * 64];

__device__ __forceinline__ float lrelu(float x) { return x > 0.f ? x : 0.2f * x; }
__device__ __forceinline__ float warpMax(float v) {
#pragma unroll
  for (int o = 16; o; o >>= 1) v = fmaxf(v, __shfl_xor_sync(0xffffffffu, v, o));
  return v;
}
__device__ __forceinline__ float warpSum(float v) {
#pragma unroll
  for (int o = 16; o; o >>= 1) v += __shfl_xor_sync(0xffffffffu, v, o);
  return v;
}

// ---------------- CSR build ----------------
__global__ void k_init() {
  int i = blockIdx.x * blockDim.x + threadIdx.x;
  if (i < NN) g_counts[i] = 0;
  if (i < BB * SS * DD) g_pooled[i] = 0.f;
  if (i < BB) g_batchcnt[i] = 0;
}

__global__ void k_hist(const int* __restrict__ ei, const int* __restrict__ batch) {
  int i = blockIdx.x * blockDim.x + threadIdx.x;
  if (i < EE) atomicAdd(&g_counts[ei[EE + i]], 1);
  if (i < NN) atomicAdd(&g_batchcnt[batch[i]], 1);
}

__global__ void k_scan() {  // single block, 1024 threads: exclusive scan of g_counts
  __shared__ int wsum[32];
  __shared__ int carry;
  int tid = threadIdx.x, lane = tid & 31, wid = tid >> 5;
  if (tid == 0) carry = 0;
  __syncthreads();
  for (int base = 0; base < NN; base += 1024) {
    int i = base + tid;
    int v = (i < NN) ? g_counts[i] : 0;
    int incl = v;
#pragma unroll
    for (int o = 1; o < 32; o <<= 1) { int u = __shfl_up_sync(0xffffffffu, incl, o); if (lane >= o) incl += u; }
    if (lane == 31) wsum[wid] = incl;
    __syncthreads();
    if (wid == 0) {
      int ws = wsum[lane];
      int wi = ws;
#pragma unroll
      for (int o = 1; o < 32; o <<= 1) { int u = __shfl_up_sync(0xffffffffu, wi, o); if (lane >= o) wi += u; }
      wsum[lane] = wi - ws;
    }
    __syncthreads();
    int excl = incl - v + wsum[wid] + carry;
    if (i < NN) { g_rowptr[i] = excl; g_wpos[i] = excl; }
    __syncthreads();
    if (tid == 1023) carry = excl + v;
    __syncthreads();
  }
  if (threadIdx.x == 0) g_rowptr[NN] = carry;
}

__global__ void k_scatter(const int* __restrict__ ei) {
  int i = blockIdx.x * blockDim.x + threadIdx.x;
  if (i >= EE) return;
  int d = ei[EE + i];
  int p = atomicAdd(&g_wpos[d], 1);
  g_col[p] = ei[i];
}

// ---------------- GEMM1: h1 = x @ W1 ; per-node attn scores ----------------
__global__ __launch_bounds__(256) void k_gemm1(const float* __restrict__ x,
                                               const float* __restrict__ W1,
                                               const float* __restrict__ as1,
                                               const float* __restrict__ ad1) {
  __shared__ float W1s[FF * HC];
  __shared__ float asS[HC], adS[HC];
  __shared__ float xs[FF];
  __shared__ float rs[HC], rd[HC];
  int tid = threadIdx.x;
  for (int i = tid; i < FF * HC; i += 256) W1s[i] = W1[i];
  asS[tid] = as1[tid];
  adS[tid] = ad1[tid];
  __syncthreads();
  int n0 = blockIdx.x * 20;
  for (int nn = 0; nn < 20; nn++) {
    int n = n0 + nn;
    if (tid < FF) xs[tid] = x[n * FF + tid];
    __syncthreads();
    float acc = 0.f;
#pragma unroll
    for (int k = 0; k < FF; k++) acc += xs[k] * W1s[k * HC + tid];
    g_h1[(size_t)n * HC + tid] = acc;
    rs[tid] = acc * asS[tid];
    rd[tid] = acc * adS[tid];
    __syncthreads();
    if ((tid & 63) < 32) {  // even warps: reduce 64-wide head groups
      float v = rs[tid] + rs[tid + 32];
      float u = rd[tid] + rd[tid + 32];
#pragma unroll
      for (int o = 16; o; o >>= 1) {
        v += __shfl_down_sync(0xffffffffu, v, o);
        u += __shfl_down_sync(0xffffffffu, u, o);
      }
      if ((tid & 31) == 0) {
        int h = tid >> 6;
        ((float*)g_ssrc1)[n * 4 + h] = v;
        ((float*)g_sdst1)[n * 4 + h] = u;
      }
    }
    __syncthreads();
  }
}

// ---------------- GAT1 aggregation: warp per dst node ----------------
__global__ __launch_bounds__(256) void k_gat1(const float* __restrict__ b1) {
  int gw = (blockIdx.x * blockDim.x + threadIdx.x) >> 5;
  if (gw >= NN) return;
  int lane = threadIdx.x & 31;
  int base = g_rowptr[gw];
  int deg = g_rowptr[gw + 1] - base;
  float4 sd = g_sdst1[gw];

  // pass 1: per-head max (incl. self loop at virtual index deg)
  float m0 = -1e30f, m1 = -1e30f, m2 = -1e30f, m3 = -1e30f;
  for (int i = lane; i <= deg; i += 32) {
    int s = (i < deg) ? g_col[base + i] : gw;
    float4 ss = g_ssrc1[s];
    m0 = fmaxf(m0, lrelu(ss.x + sd.x));
    m1 = fmaxf(m1, lrelu(ss.y + sd.y));
    m2 = fmaxf(m2, lrelu(ss.z + sd.z));
    m3 = fmaxf(m3, lrelu(ss.w + sd.w));
  }
  m0 = warpMax(m0); m1 = warpMax(m1); m2 = warpMax(m2); m3 = warpMax(m3);

  // pass 2: exp + sum, stage exps to global alpha buffer
  float s0 = 0, s1 = 0, s2 = 0, s3 = 0;
  float4 selfe = make_float4(0, 0, 0, 0);
  for (int i = lane; i <= deg; i += 32) {
    int s = (i < deg) ? g_col[base + i] : gw;
    float4 ss = g_ssrc1[s];
    float e0 = __expf(lrelu(ss.x + sd.x) - m0);
    float e1 = __expf(lrelu(ss.y + sd.y) - m1);
    float e2 = __expf(lrelu(ss.z + sd.z) - m2);
    float e3 = __expf(lrelu(ss.w + sd.w) - m3);
    s0 += e0; s1 += e1; s2 += e2; s3 += e3;
    if (i < deg) g_alpha[base + i] = make_float4(e0, e1, e2, e3);
    else selfe = make_float4(e0, e1, e2, e3);
  }
  s0 = warpSum(s0); s1 = warpSum(s1); s2 = warpSum(s2); s3 = warpSum(s3);
  int sl = deg & 31;
  selfe.x = __shfl_sync(0xffffffffu, selfe.x, sl);
  selfe.y = __shfl_sync(0xffffffffu, selfe.y, sl);
  selfe.z = __shfl_sync(0xffffffffu, selfe.z, sl);
  selfe.w = __shfl_sync(0xffffffffu, selfe.w, sl);
  __syncwarp();
  float i0 = 1.f / s0, i1 = 1.f / s1, i2 = 1.f / s2, i3 = 1.f / s3;

  // pass 3: weighted gather-accumulate (coalesced 1KB rows, L2 resident)
  float acc[8] = {0, 0, 0, 0, 0, 0, 0, 0};
#pragma unroll 4
  for (int e = 0; e < deg; e++) {
    int s = g_col[base + e];
    float4 a = g_alpha[base + e];
    float w0 = a.x * i0, w1 = a.y * i1, w2 = a.z * i2, w3 = a.w * i3;
    const float* hr = g_h1 + (size_t)s * HC + lane;
    acc[0] += w0 * hr[0];   acc[1] += w0 * hr[32];
    acc[2] += w1 * hr[64];  acc[3] += w1 * hr[96];
    acc[4] += w2 * hr[128]; acc[5] += w2 * hr[160];
    acc[6] += w3 * hr[192]; acc[7] += w3 * hr[224];
  }
  {  // self loop
    float w0 = selfe.x * i0, w1 = selfe.y * i1, w2 = selfe.z * i2, w3 = selfe.w * i3;
    const float* hr = g_h1 + (size_t)gw * HC + lane;
    acc[0] += w0 * hr[0];   acc[1] += w0 * hr[32];
    acc[2] += w1 * hr[64];  acc[3] += w1 * hr[96];
    acc[4] += w2 * hr[128]; acc[5] += w2 * hr[160];
    acc[6] += w3 * hr[192]; acc[7] += w3 * hr[224];
  }
  float* orow = g_out1 + (size_t)gw * HC + lane;
#pragma unroll
  for (int j = 0; j < 8; j++)
    orow[j * 32] = fmaxf(acc[j] + b1[j * 32 + lane], 0.f);  // + b1, relu
}

// ---------------- GEMM2: h2 = out1 @ W2 (tiled fp32) ----------------
__global__ __launch_bounds__(256) void k_gemm2(const float* __restrict__ W2) {
  __shared__ float As[64][33];
  __shared__ float Bs[32][64];
  int tid = threadIdx.x;
  int tx = tid & 15, ty = tid >> 4;
  int m0 = blockIdx.x * 64;
  float acc[4][4] = {};
  for (int k0 = 0; k0 < HC; k0 += 32) {
    for (int i = tid; i < 64 * 32; i += 256) {
      int r = i >> 5, c = i & 31;
      int row = m0 + r;
      As[r][c] = (row < NN) ? g_out1[(size_t)row * HC + k0 + c] : 0.f;
    }
    for (int i = tid; i < 32 * 64; i += 256) {
      int r = i >> 6, c = i & 63;
      Bs[r][c] = W2[(k0 + r) * 64 + c];
    }
    __syncthreads();
#pragma unroll
    for (int k = 0; k < 32; k++) {
      float a[4], b[4];
#pragma unroll
      for (int i = 0; i < 4; i++) a[i] = As[ty * 4 + i][k];
#pragma unroll
      for (int j = 0; j < 4; j++) b[j] = Bs[k][tx * 4 + j];
#pragma unroll
      for (int i = 0; i < 4; i++)
#pragma unroll
        for (int j = 0; j < 4; j++) acc[i][j] += a[i] * b[j];
    }
    __syncthreads();
  }
#pragma unroll
  for (int i = 0; i < 4; i++) {
    int row = m0 + ty * 4 + i;
    if (row < NN)
#pragma unroll
      for (int j = 0; j < 4; j++) g_h2[(size_t)row * 64 + tx * 4 + j] = acc[i][j];
  }
}

// ---------------- per-node scores for GAT2 ----------------
__global__ __launch_bounds__(256) void k_scores2(const float* __restrict__ as2,
                                                 const float* __restrict__ ad2) {
  int w = (blockIdx.x * blockDim.x + threadIdx.x) >> 5;
  if (w >= NN) return;
  int lane = threadIdx.x & 31;
  float v0 = g_h2[(size_t)w * 64 + lane];
  float v1 = g_h2[(size_t)w * 64 + 32 + lane];
  float ps = v0 * as2[lane] + v1 * as2[lane + 32];
  float pd = v0 * ad2[lane] + v1 * ad2[lane + 32];
  ps = warpSum(ps);
  pd = warpSum(pd);
  if (lane == 0) { g_ssrc2[w] = ps; g_sdst2[w] = pd; }
}

// ---------------- GAT2 aggregation + mean-pool scatter ----------------
__global__ __launch_bounds__(256) void k_gat2(const float* __restrict__ b2,
                                              const int* __restrict__ batch, int t) {
  int gw = (blockIdx.x * blockDim.x + threadIdx.x) >> 5;
  if (gw >= NN) return;
  int lane = threadIdx.x & 31;
  int base = g_rowptr[gw];
  int deg = g_rowptr[gw + 1] - base;
  float sd = g_sdst2[gw];
  float* alpha = (float*)g_alpha;

  float m = -1e30f;
  for (int i = lane; i <= deg; i += 32) {
    int s = (i < deg) ? g_col[base + i] : gw;
    m = fmaxf(m, lrelu(g_ssrc2[s] + sd));
  }
  m = warpMax(m);

  float sum = 0.f, selfe = 0.f;
  for (int i = lane; i <= deg; i += 32) {
    int s = (i < deg) ? g_col[base + i] : gw;
    float e = __expf(lrelu(g_ssrc2[s] + sd) - m);
    sum += e;
    if (i < deg) alpha[base + i] = e;
    else selfe = e;
  }
  sum = warpSum(sum);
  selfe = __shfl_sync(0xffffffffu, selfe, deg & 31);
  __syncwarp();
  float inv = 1.f / sum;

  float a0 = 0.f, a1 = 0.f;
#pragma unroll 4
  for (int e = 0; e < deg; e++) {
    int s = g_col[base + e];
    float w = alpha[base + e] * inv;
    const float* hr = g_h2 + (size_t)s * 64 + lane;
    a0 += w * hr[0];
    a1 += w * hr[32];
  }
  {
    float w = selfe * inv;
    const float* hr = g_h2 + (size_t)gw * 64 + lane;
    a0 += w * hr[0];
    a1 += w * hr[32];
  }
  int b = batch[gw];
  atomicAdd(&g_pooled[b * (SS * DD) + t * DD + lane], a0 + b2[lane]);
  atomicAdd(&g_pooled[b * (SS * DD) + t * DD + lane + 32], a1 + b2[lane + 32]);
}

// ---------------- final: MHA + residual + LN + temporal mean + proj ----------------
__global__ __launch_bounds__(256) void k_final(const float* __restrict__ ipw, const float* __restrict__ ipb,
                                               const float* __restrict__ opw, const float* __restrict__ opb,
                                               const float* __restrict__ lng, const float* __restrict__ lnb,
                                               const float* __restrict__ pw,  const float* __restrict__ pb,
                                               float* __restrict__ out) {
  __shared__ float sx[96 * 64];
  __shared__ float sym[16 * 64];
  __shared__ float sinv[16];
  int tid = threadIdx.x;
  if (tid < 16) {
    int c = g_batchcnt[tid];
    sinv[tid] = 1.f / (c > 0 ? (float)c : 1.f);
  }
  for (int i = tid; i < 16 * 64; i += 256) sym[i] = 0.f;
  __syncthreads();
  for (int i = tid; i < 96 * 64; i += 256) {
    int row = i >> 6;
    sx[i] = g_pooled[i] * sinv[row / 6];
  }
  __syncthreads();
  // qkv = x @ ipw^T + ipb
  for (int i = tid; i < 96 * 192; i += 256) {
    int row = i / 192, j = i - row * 192;
    float acc = ipb[j];
    const float* xr = &sx[row * 64];
    const float* wr = &ipw[j * 64];
    for (int c = 0; c < 64; c++) acc += xr[c] * wr[c];
    g_qkv[i] = acc;
  }
  __syncthreads();
  // attention: thread per (b, head)
  if (tid < 64) {
    int b = tid >> 2, h = tid & 3;
    for (int s1 = 0; s1 < 6; s1++) {
      float sc[6];
      float mx = -1e30f;
      const float* qr = &g_qkv[(b * 6 + s1) * 192 + h * 16];
      for (int s2 = 0; s2 < 6; s2++) {
        const float* kr = &g_qkv[(b * 6 + s2) * 192 + 64 + h * 16];
        float d = 0.f;
        for (int u = 0; u < 16; u++) d += qr[u] * kr[u];
        sc[s2] = d * 0.25f;
        mx = fmaxf(mx, sc[s2]);
      }
      float ssum = 0.f;
      for (int s2 = 0; s2 < 6; s2++) { sc[s2] = __expf(sc[s2] - mx); ssum += sc[s2]; }
      float invs = 1.f / ssum;
      float o[16];
      for (int u = 0; u < 16; u++) o[u] = 0.f;
      for (int s2 = 0; s2 < 6; s2++) {
        float w = sc[s2] * invs;
        const float* vr = &g_qkv[(b * 6 + s2) * 192 + 128 + h * 16];
        for (int u = 0; u < 16; u++) o[u] += w * vr[u];
      }
      float* orow = &g_go[(b * 6 + s1) * 64 + h * 16];
      for (int u = 0; u < 16; u++) orow[u] = o[u];
    }
  }
  __syncthreads();
  // out_proj + residual + LayerNorm + temporal-mean accumulate (warp per row)
  int wid = tid >> 5, lane = tid & 31;
  for (int row = wid; row < 96; row += 8) {
    const float* orow = &g_go[row * 64];
    float y0 = opb[lane], y1 = opb[lane + 32];
    for (int c = 0; c < 64; c++) {
      float ov = orow[c];
      y0 += ov * opw[lane * 64 + c];
      y1 += ov * opw[(lane + 32) * 64 + c];
    }
    y0 += sx[row * 64 + lane];
    y1 += sx[row * 64 + lane + 32];
    float s = warpSum(y0 + y1);
    float mu = s * (1.f / 64.f);
    float d0 = y0 - mu, d1 = y1 - mu;
    float vs = warpSum(d0 * d0 + d1 * d1);
    float var = vs * (1.f / 64.f);
    float r = rsqrtf(var + 1e-5f);
    float z0 = d0 * r * lng[lane] + lnb[lane];
    float z1 = d1 * r * lng[lane + 32] + lnb[lane + 32];
    int b = row / 6;
    atomicAdd(&sym[b * 64 + lane], z0 * (1.f / 6.f));
    atomicAdd(&sym[b * 64 + lane + 32], z1 * (1.f / 6.f));
  }
  __syncthreads();
  // final projection
  for (int i = tid; i < 16 * 64; i += 256) {
    int b = i >> 6, j = i & 63;
    float acc = pb[j];
    const float* yr = &sym[b * 64];
    const float* wr = &pw[j * 64];
    for (int c = 0; c < 64; c++) acc += yr[c] * wr[c];
    out[i] = acc;
  }
}

// ---------------- launch ----------------
extern "C" void kernel_launch(void* const* d_in, const int* in_sizes, int n_in,
                              void* d_out, int out_size) {
  const float* x_seq = (const float*)d_in[0];
  const int*   ei    = (const int*)d_in[1];
  const int*   batch = (const int*)d_in[2];
  const float* W1    = (const float*)d_in[3];
  const float* as1   = (const float*)d_in[4];
  const float* ad1   = (const float*)d_in[5];
  const float* b1    = (const float*)d_in[6];
  const float* W2    = (const float*)d_in[7];
  const float* as2   = (const float*)d_in[8];
  const float* ad2   = (const float*)d_in[9];
  const float* b2    = (const float*)d_in[10];
  const float* ipw   = (const float*)d_in[11];
  const float* ipb   = (const float*)d_in[12];
  const float* opw   = (const float*)d_in[13];
  const float* opb   = (const float*)d_in[14];
  const float* lng   = (const float*)d_in[15];
  const float* lnb   = (const float*)d_in[16];
  const float* pw    = (const float*)d_in[17];
  const float* pb    = (const float*)d_in[18];
  float* out = (float*)d_out;

  k_init<<<(NN + 255) / 256, 256>>>();
  k_hist<<<(EE + 255) / 256, 256>>>(ei, batch);
  k_scan<<<1, 1024>>>();
  k_scatter<<<(EE + 255) / 256, 256>>>(ei);

  for (int t = 0; t < SS; t++) {
    k_gemm1<<<NN / 20, 256>>>(x_seq + (size_t)t * NN * FF, W1, as1, ad1);
    k_gat1<<<(NN * 32 + 255) / 256, 256>>>(b1);
    k_gemm2<<<(NN + 63) / 64, 256>>>(W2);
    k_scores2<<<(NN * 32 + 255) / 256, 256>>>(as2, ad2);
    k_gat2<<<(NN * 32 + 255) / 256, 256>>>(b2, batch, t);
  }
  k_final<<<1, 256>>>(ipw, ipb, opw, opb, lng, lnb, pw, pb, out);
}

// round 2
// speedup vs baseline: 1.1443x; 1.1443x over previous
#include <cuda_runtime.h>
#include <cstdint>

#define NN 20000
#define EE 640000
#define FF 32
#define HH 4
#define CC 64
#define SS 6
#define BB 16
#define DD 64
#define HC 256   // H*C

// ---------------- device scratch ----------------
__device__ int    g_counts[NN];
__device__ int    g_rowptr[NN + 1];
__device__ int    g_wpos[NN];
__device__ int    g_col[EE];
__device__ int    g_batchcnt[BB];
__device__ float  g_h1[(size_t)NN * HC];     // x @ W1            20.48 MB
__device__ float  g_out1[(size_t)NN * HC];   // relu(gat1 out)    20.48 MB
__device__ float4 g_ssrc1[NN];
__device__ float4 g_sdst1[NN];
__device__ float  g_h2[(size_t)NN * CC];     // out1 @ W2          5.12 MB
__device__ float  g_ssrc2[NN];
__device__ float  g_sdst2[NN];
__device__ float  g_pooled[BB * SS * DD];
__device__ float  g_qkv[96 * 192];
__device__ float  g_go[96 * 64];

__device__ __forceinline__ float lrelu(float x) { return x > 0.f ? x : 0.2f * x; }
__device__ __forceinline__ float warpSum(float v) {
#pragma unroll
  for (int o = 16; o; o >>= 1) v += __shfl_xor_sync(0xffffffffu, v, o);
  return v;
}

// ---------------- CSR build ----------------
__global__ void k_init() {
  int i = blockIdx.x * blockDim.x + threadIdx.x;
  if (i < NN) g_counts[i] = 0;
  if (i < BB * SS * DD) g_pooled[i] = 0.f;
  if (i < BB) g_batchcnt[i] = 0;
}

__global__ void k_hist(const int* __restrict__ ei, const int* __restrict__ batch) {
  int i = blockIdx.x * blockDim.x + threadIdx.x;
  if (i < EE) atomicAdd(&g_counts[ei[EE + i]], 1);
  if (i < NN) atomicAdd(&g_batchcnt[batch[i]], 1);
}

__global__ void k_scan() {  // single block, 1024 threads: exclusive scan
  __shared__ int wsum[32];
  __shared__ int carry;
  int tid = threadIdx.x, lane = tid & 31, wid = tid >> 5;
  if (tid == 0) carry = 0;
  __syncthreads();
  for (int base = 0; base < NN; base += 1024) {
    int i = base + tid;
    int v = (i < NN) ? g_counts[i] : 0;
    int incl = v;
#pragma unroll
    for (int o = 1; o < 32; o <<= 1) { int u = __shfl_up_sync(0xffffffffu, incl, o); if (lane >= o) incl += u; }
    if (lane == 31) wsum[wid] = incl;
    __syncthreads();
    if (wid == 0) {
      int ws = wsum[lane];
      int wi = ws;
#pragma unroll
      for (int o = 1; o < 32; o <<= 1) { int u = __shfl_up_sync(0xffffffffu, wi, o); if (lane >= o) wi += u; }
      wsum[lane] = wi - ws;
    }
    __syncthreads();
    int excl = incl - v + wsum[wid] + carry;
    if (i < NN) { g_rowptr[i] = excl; g_wpos[i] = excl; }
    __syncthreads();
    if (tid == 1023) carry = excl + v;
    __syncthreads();
  }
  if (threadIdx.x == 0) g_rowptr[NN] = carry;
}

__global__ void k_scatter(const int* __restrict__ ei) {
  int i = blockIdx.x * blockDim.x + threadIdx.x;
  if (i >= EE) return;
  int d = ei[EE + i];
  int p = atomicAdd(&g_wpos[d], 1);
  g_col[p] = ei[i];
}

// ---------------- GEMM1: h1 = x @ W1 ; fused per-head attn scores ----------------
// 64x256x32 per block, 8x8 per thread.
__global__ __launch_bounds__(256) void k_gemm1(const float* __restrict__ x,
                                               const float* __restrict__ W1,
                                               const float* __restrict__ as1,
                                               const float* __restrict__ ad1) {
  __shared__ float Ws[FF * HC];    // 32 KB
  __shared__ float Xs[64][33];
  int tid = threadIdx.x;
  for (int i = tid; i < FF * HC / 4; i += 256) ((float4*)Ws)[i] = ((const float4*)W1)[i];
  int m0 = blockIdx.x * 64;
  for (int i = tid; i < 512; i += 256) {      // 64 rows x 8 float4
    int r = i >> 3, c4 = i & 7;
    float4 v = make_float4(0.f, 0.f, 0.f, 0.f);
    if (m0 + r < NN) v = ((const float4*)(x + (size_t)(m0 + r) * FF))[c4];
    Xs[r][c4 * 4 + 0] = v.x; Xs[r][c4 * 4 + 1] = v.y;
    Xs[r][c4 * 4 + 2] = v.z; Xs[r][c4 * 4 + 3] = v.w;
  }
  __syncthreads();
  int tx = tid & 31, ty = tid >> 5;            // tx: 32 col-groups of 8, ty: 8 row-groups of 8
  float acc[8][8] = {};
#pragma unroll
  for (int k = 0; k < FF; k++) {
    float a[8];
#pragma unroll
    for (int i = 0; i < 8; i++) a[i] = Xs[ty * 8 + i][k];
    float4 b0 = *(const float4*)(Ws + k * HC + tx * 8);
    float4 b1v = *(const float4*)(Ws + k * HC + tx * 8 + 4);
    float b[8] = {b0.x, b0.y, b0.z, b0.w, b1v.x, b1v.y, b1v.z, b1v.w};
#pragma unroll
    for (int i = 0; i < 8; i++)
#pragma unroll
      for (int j = 0; j < 8; j++) acc[i][j] += a[i] * b[j];
  }
  // attention score epilogue: head = tx/8 (cols tx*8.. within one 64-wide head)
  float asr[8], adr[8];
#pragma unroll
  for (int j = 0; j < 8; j++) { asr[j] = __ldg(as1 + tx * 8 + j); adr[j] = __ldg(ad1 + tx * 8 + j); }
#pragma unroll
  for (int i = 0; i < 8; i++) {
    int row = m0 + ty * 8 + i;
    float ps = 0.f, pd = 0.f;
#pragma unroll
    for (int j = 0; j < 8; j++) { ps += acc[i][j] * asr[j]; pd += acc[i][j] * adr[j]; }
#pragma unroll
    for (int o = 4; o; o >>= 1) {
      ps += __shfl_down_sync(0xffffffffu, ps, o, 8);
      pd += __shfl_down_sync(0xffffffffu, pd, o, 8);
    }
    if (row < NN) {
      if ((tx & 7) == 0) {
        ((float*)&g_ssrc1[row])[tx >> 3] = ps;
        ((float*)&g_sdst1[row])[tx >> 3] = pd;
      }
      float4 o0 = {acc[i][0], acc[i][1], acc[i][2], acc[i][3]};
      float4 o1 = {acc[i][4], acc[i][5], acc[i][6], acc[i][7]};
      float4* dst = (float4*)(g_h1 + (size_t)row * HC + tx * 8);
      dst[0] = o0; dst[1] = o1;
    }
  }
}

// ---------------- GAT1: single-pass softmax-aggregate, warp per dst node ----------------
__global__ __launch_bounds__(256) void k_gat1(const float* __restrict__ b1) {
  __shared__ int    sIdx[8][32];
  __shared__ float4 sE[8][32];
  int wslot = threadIdx.x >> 5;
  int gw = (blockIdx.x * blockDim.x + threadIdx.x) >> 5;
  if (gw >= NN) return;
  int lane = threadIdx.x & 31;
  int base = g_rowptr[gw];
  int deg = g_rowptr[gw + 1] - base;           // +1 virtual self loop at index deg
  float4 sd = g_sdst1[gw];
  int h01 = lane >> 4;                          // which head within pair
  const float4* h1v = (const float4*)g_h1;
  float4 acc0 = {0, 0, 0, 0}, acc1 = {0, 0, 0, 0};
  float s0 = 0, s1 = 0, s2 = 0, s3 = 0;

  for (int c0 = 0; c0 <= deg; c0 += 32) {
    int i = c0 + lane;
    float4 e4 = {0, 0, 0, 0};
    int s = gw;
    if (i <= deg) {
      s = (i < deg) ? g_col[base + i] : gw;
      float4 ss = g_ssrc1[s];
      e4.x = __expf(lrelu(ss.x + sd.x));
      e4.y = __expf(lrelu(ss.y + sd.y));
      e4.z = __expf(lrelu(ss.z + sd.z));
      e4.w = __expf(lrelu(ss.w + sd.w));
      s0 += e4.x; s1 += e4.y; s2 += e4.z; s3 += e4.w;
    }
    sIdx[wslot][lane] = s;
    sE[wslot][lane] = e4;
    __syncwarp();
    int cnt = min(32, deg + 1 - c0);
#pragma unroll 4
    for (int j = 0; j < cnt; j++) {
      int sj = sIdx[wslot][j];
      const float* ep = (const float*)&sE[wslot][j];
      float wa = ep[h01];
      float wb = ep[2 + h01];
      const float4* hr = h1v + (size_t)sj * 64;
      float4 va = hr[lane];
      float4 vb = hr[32 + lane];
      acc0.x += wa * va.x; acc0.y += wa * va.y; acc0.z += wa * va.z; acc0.w += wa * va.w;
      acc1.x += wb * vb.x; acc1.y += wb * vb.y; acc1.z += wb * vb.z; acc1.w += wb * vb.w;
    }
    __syncwarp();
  }
  s0 = warpSum(s0); s1 = warpSum(s1); s2 = warpSum(s2); s3 = warpSum(s3);
  float ia = (h01 == 0) ? (1.f / s0) : (1.f / s1);
  float ib = (h01 == 0) ? (1.f / s2) : (1.f / s3);
  float4 bb0 = ((const float4*)b1)[lane];
  float4 bb1 = ((const float4*)b1)[32 + lane];
  float4 o0, o1;
  o0.x = fmaxf(acc0.x * ia + bb0.x, 0.f);
  o0.y = fmaxf(acc0.y * ia + bb0.y, 0.f);
  o0.z = fmaxf(acc0.z * ia + bb0.z, 0.f);
  o0.w = fmaxf(acc0.w * ia + bb0.w, 0.f);
  o1.x = fmaxf(acc1.x * ib + bb1.x, 0.f);
  o1.y = fmaxf(acc1.y * ib + bb1.y, 0.f);
  o1.z = fmaxf(acc1.z * ib + bb1.z, 0.f);
  o1.w = fmaxf(acc1.w * ib + bb1.w, 0.f);
  float4* dst = (float4*)g_out1 + (size_t)gw * 64;
  dst[lane] = o0;
  dst[32 + lane] = o1;
}

// ---------------- GEMM2: h2 = out1 @ W2 ; fused GAT2 scores ----------------
__global__ __launch_bounds__(256) void k_gemm2(const float* __restrict__ W2,
                                               const float* __restrict__ as2,
                                               const float* __restrict__ ad2) {
  __shared__ float As[64][33];
  __shared__ float Bs[32][64];
  int tid = threadIdx.x;
  int tx = tid & 15, ty = tid >> 4;
  int m0 = blockIdx.x * 64;
  float acc[4][4] = {};
  for (int k0 = 0; k0 < HC; k0 += 32) {
    for (int i = tid; i < 64 * 32; i += 256) {
      int r = i >> 5, c = i & 31;
      int row = m0 + r;
      As[r][c] = (row < NN) ? g_out1[(size_t)row * HC + k0 + c] : 0.f;
    }
    for (int i = tid; i < 32 * 64; i += 256) {
      int r = i >> 6, c = i & 63;
      Bs[r][c] = W2[(k0 + r) * 64 + c];
    }
    __syncthreads();
#pragma unroll
    for (int k = 0; k < 32; k++) {
      float a[4], b[4];
#pragma unroll
      for (int i = 0; i < 4; i++) a[i] = As[ty * 4 + i][k];
#pragma unroll
      for (int j = 0; j < 4; j++) b[j] = Bs[k][tx * 4 + j];
#pragma unroll
      for (int i = 0; i < 4; i++)
#pragma unroll
        for (int j = 0; j < 4; j++) acc[i][j] += a[i] * b[j];
    }
    __syncthreads();
  }
  float asr[4], adr[4];
#pragma unroll
  for (int j = 0; j < 4; j++) { asr[j] = __ldg(as2 + tx * 4 + j); adr[j] = __ldg(ad2 + tx * 4 + j); }
#pragma unroll
  for (int i = 0; i < 4; i++) {
    int row = m0 + ty * 4 + i;
    float ps = 0.f, pd = 0.f;
#pragma unroll
    for (int j = 0; j < 4; j++) { ps += acc[i][j] * asr[j]; pd += acc[i][j] * adr[j]; }
#pragma unroll
    for (int o = 8; o; o >>= 1) {
      ps += __shfl_down_sync(0xffffffffu, ps, o, 16);
      pd += __shfl_down_sync(0xffffffffu, pd, o, 16);
    }
    if (row < NN) {
      if (tx == 0) { g_ssrc2[row] = ps; g_sdst2[row] = pd; }
#pragma unroll
      for (int j = 0; j < 4; j++) g_h2[(size_t)row * 64 + tx * 4 + j] = acc[i][j];
    }
  }
}

// ---------------- GAT2: single-pass aggregate + mean-pool scatter ----------------
__global__ __launch_bounds__(256) void k_gat2(const float* __restrict__ b2,
                                              const int* __restrict__ batch, int t) {
  __shared__ int   sIdx[8][32];
  __shared__ float sEs[8][32];
  int wslot = threadIdx.x >> 5;
  int gw = (blockIdx.x * blockDim.x + threadIdx.x) >> 5;
  if (gw >= NN) return;
  int lane = threadIdx.x & 31;
  int base = g_rowptr[gw];
  int deg = g_rowptr[gw + 1] - base;
  float sd = g_sdst2[gw];
  const float2* h2v = (const float2*)g_h2;
  float2 acc = {0, 0};
  float sum = 0.f;

  for (int c0 = 0; c0 <= deg; c0 += 32) {
    int i = c0 + lane;
    float e = 0.f;
    int s = gw;
    if (i <= deg) {
      s = (i < deg) ? g_col[base + i] : gw;
      e = __expf(lrelu(g_ssrc2[s] + sd));
      sum += e;
    }
    sIdx[wslot][lane] = s;
    sEs[wslot][lane] = e;
    __syncwarp();
    int cnt = min(32, deg + 1 - c0);
#pragma unroll 4
    for (int j = 0; j < cnt; j++) {
      int sj = sIdx[wslot][j];
      float ej = sEs[wslot][j];
      float2 v = h2v[(size_t)sj * 32 + lane];
      acc.x += ej * v.x;
      acc.y += ej * v.y;
    }
    __syncwarp();
  }
  sum = warpSum(sum);
  float inv = 1.f / sum;
  int b = batch[gw];
  float v0 = acc.x * inv + b2[lane * 2];
  float v1 = acc.y * inv + b2[lane * 2 + 1];
  atomicAdd(&g_pooled[b * (SS * DD) + t * DD + lane * 2], v0);
  atomicAdd(&g_pooled[b * (SS * DD) + t * DD + lane * 2 + 1], v1);
}

// ---------------- final: MHA + residual + LN + temporal mean + proj ----------------
__global__ __launch_bounds__(256) void k_final(const float* __restrict__ ipw, const float* __restrict__ ipb,
                                               const float* __restrict__ opw, const float* __restrict__ opb,
                                               const float* __restrict__ lng, const float* __restrict__ lnb,
                                               const float* __restrict__ pw,  const float* __restrict__ pb,
                                               float* __restrict__ out) {
  __shared__ float sx[96 * 64];
  __shared__ float sym[16 * 64];
  __shared__ float sinv[16];
  int tid = threadIdx.x;
  if (tid < 16) {
    int c = g_batchcnt[tid];
    sinv[tid] = 1.f / (c > 0 ? (float)c : 1.f);
  }
  for (int i = tid; i < 16 * 64; i += 256) sym[i] = 0.f;
  __syncthreads();
  for (int i = tid; i < 96 * 64; i += 256) {
    int row = i >> 6;
    sx[i] = g_pooled[i] * sinv[row / 6];
  }
  __syncthreads();
  for (int i = tid; i < 96 * 192; i += 256) {
    int row = i / 192, j = i - row * 192;
    float acc = ipb[j];
    const float* xr = &sx[row * 64];
    const float* wr = &ipw[j * 64];
    for (int c = 0; c < 64; c++) acc += xr[c] * wr[c];
    g_qkv[i] = acc;
  }
  __syncthreads();
  if (tid < 64) {
    int b = tid >> 2, h = tid & 3;
    for (int s1 = 0; s1 < 6; s1++) {
      float sc[6];
      float mx = -1e30f;
      const float* qr = &g_qkv[(b * 6 + s1) * 192 + h * 16];
      for (int s2 = 0; s2 < 6; s2++) {
        const float* kr = &g_qkv[(b * 6 + s2) * 192 + 64 + h * 16];
        float d = 0.f;
        for (int u = 0; u < 16; u++) d += qr[u] * kr[u];
        sc[s2] = d * 0.25f;
        mx = fmaxf(mx, sc[s2]);
      }
      float ssum = 0.f;
      for (int s2 = 0; s2 < 6; s2++) { sc[s2] = __expf(sc[s2] - mx); ssum += sc[s2]; }
      float invs = 1.f / ssum;
      float o[16];
      for (int u = 0; u < 16; u++) o[u] = 0.f;
      for (int s2 = 0; s2 < 6; s2++) {
        float w = sc[s2] * invs;
        const float* vr = &g_qkv[(b * 6 + s2) * 192 + 128 + h * 16];
        for (int u = 0; u < 16; u++) o[u] += w * vr[u];
      }
      float* orow = &g_go[(b * 6 + s1) * 64 + h * 16];
      for (int u = 0; u < 16; u++) orow[u] = o[u];
    }
  }
  __syncthreads();
  int wid = tid >> 5, lane = tid & 31;
  for (int row = wid; row < 96; row += 8) {
    const float* orow = &g_go[row * 64];
    float y0 = opb[lane], y1 = opb[lane + 32];
    for (int c = 0; c < 64; c++) {
      float ov = orow[c];
      y0 += ov * opw[lane * 64 + c];
      y1 += ov * opw[(lane + 32) * 64 + c];
    }
    y0 += sx[row * 64 + lane];
    y1 += sx[row * 64 + lane + 32];
    float s = warpSum(y0 + y1);
    float mu = s * (1.f / 64.f);
    float d0 = y0 - mu, d1 = y1 - mu;
    float vs = warpSum(d0 * d0 + d1 * d1);
    float var = vs * (1.f / 64.f);
    float r = rsqrtf(var + 1e-5f);
    float z0 = d0 * r * lng[lane] + lnb[lane];
    float z1 = d1 * r * lng[lane + 32] + lnb[lane + 32];
    int b = row / 6;
    atomicAdd(&sym[b * 64 + lane], z0 * (1.f / 6.f));
    atomicAdd(&sym[b * 64 + lane + 32], z1 * (1.f / 6.f));
  }
  __syncthreads();
  for (int i = tid; i < 16 * 64; i += 256) {
    int b = i >> 6, j = i & 63;
    float acc = pb[j];
    const float* yr = &sym[b * 64];
    const float* wr = &pw[j * 64];
    for (int c = 0; c < 64; c++) acc += yr[c] * wr[c];
    out[i] = acc;
  }
}

// ---------------- launch ----------------
extern "C" void kernel_launch(void* const* d_in, const int* in_sizes, int n_in,
                              void* d_out, int out_size) {
  const float* x_seq = (const float*)d_in[0];
  const int*   ei    = (const int*)d_in[1];
  const int*   batch = (const int*)d_in[2];
  const float* W1    = (const float*)d_in[3];
  const float* as1   = (const float*)d_in[4];
  const float* ad1   = (const float*)d_in[5];
  const float* b1    = (const float*)d_in[6];
  const float* W2    = (const float*)d_in[7];
  const float* as2   = (const float*)d_in[8];
  const float* ad2   = (const float*)d_in[9];
  const float* b2    = (const float*)d_in[10];
  const float* ipw   = (const float*)d_in[11];
  const float* ipb   = (const float*)d_in[12];
  const float* opw   = (const float*)d_in[13];
  const float* opb   = (const float*)d_in[14];
  const float* lng   = (const float*)d_in[15];
  const float* lnb   = (const float*)d_in[16];
  const float* pw    = (const float*)d_in[17];
  const float* pb    = (const float*)d_in[18];
  float* out = (float*)d_out;

  k_init<<<(NN + 255) / 256, 256>>>();
  k_hist<<<(EE + 255) / 256, 256>>>(ei, batch);
  k_scan<<<1, 1024>>>();
  k_scatter<<<(EE + 255) / 256, 256>>>(ei);

  for (int t = 0; t < SS; t++) {
    k_gemm1<<<(NN + 63) / 64, 256>>>(x_seq + (size_t)t * NN * FF, W1, as1, ad1);
    k_gat1<<<(NN * 32 + 255) / 256, 256>>>(b1);
    k_gemm2<<<(NN + 63) / 64, 256>>>(W2, as2, ad2);
    k_gat2<<<(NN * 32 + 255) / 256, 256>>>(b2, batch, t);
  }
  k_final<<<1, 256>>>(ipw, ipb, opw, opb, lng, lnb, pw, pb, out);
}

// round 3
// speedup vs baseline: 1.1864x; 1.0368x over previous
#include <cuda_runtime.h>
#include <cuda_fp16.h>
#include <cstdint>

#define NN 20000
#define EE 640000
#define FF 32
#define HH 4
#define CC 64
#define SS 6
#define BB 16
#define DD 64
#define HC 256   // H*C

// ---------------- device scratch ----------------
__device__ int    g_counts[NN];
__device__ int    g_rowptr[NN + 1];
__device__ int    g_wpos[NN];
__device__ int    g_col[EE];
__device__ int    g_batchcnt[BB];
__device__ __half g_h1[(size_t)NN * HC];     // x @ W1 (fp16)     10.24 MB
__device__ __half g_out1[(size_t)NN * HC];   // relu(gat1) fp16   10.24 MB
__device__ float4 g_ssrc1[NN];
__device__ float4 g_sdst1[NN];
__device__ __half g_h2[(size_t)NN * CC];     // out1 @ W2 fp16     2.56 MB
__device__ float  g_ssrc2[NN];
__device__ float  g_sdst2[NN];
__device__ float  g_pooled[BB * SS * DD];
__device__ float  g_qkv[96 * 192];
__device__ float  g_go[96 * 64];

__device__ __forceinline__ float lrelu(float x) { return x > 0.f ? x : 0.2f * x; }
__device__ __forceinline__ float warpSum(float v) {
#pragma unroll
  for (int o = 16; o; o >>= 1) v += __shfl_xor_sync(0xffffffffu, v, o);
  return v;
}

// ---------------- CSR build ----------------
__global__ void k_init() {
  int i = blockIdx.x * blockDim.x + threadIdx.x;
  if (i < NN) g_counts[i] = 0;
  if (i < BB * SS * DD) g_pooled[i] = 0.f;
  if (i < BB) g_batchcnt[i] = 0;
}

__global__ void k_hist(const int* __restrict__ ei, const int* __restrict__ batch) {
  int i = blockIdx.x * blockDim.x + threadIdx.x;
  if (i < EE) atomicAdd(&g_counts[ei[EE + i]], 1);
  if (i < NN) atomicAdd(&g_batchcnt[batch[i]], 1);
}

__global__ void k_scan() {
  __shared__ int wsum[32];
  __shared__ int carry;
  int tid = threadIdx.x, lane = tid & 31, wid = tid >> 5;
  if (tid == 0) carry = 0;
  __syncthreads();
  for (int base = 0; base < NN; base += 1024) {
    int i = base + tid;
    int v = (i < NN) ? g_counts[i] : 0;
    int incl = v;
#pragma unroll
    for (int o = 1; o < 32; o <<= 1) { int u = __shfl_up_sync(0xffffffffu, incl, o); if (lane >= o) incl += u; }
    if (lane == 31) wsum[wid] = incl;
    __syncthreads();
    if (wid == 0) {
      int ws = wsum[lane];
      int wi = ws;
#pragma unroll
      for (int o = 1; o < 32; o <<= 1) { int u = __shfl_up_sync(0xffffffffu, wi, o); if (lane >= o) wi += u; }
      wsum[lane] = wi - ws;
    }
    __syncthreads();
    int excl = incl - v + wsum[wid] + carry;
    if (i < NN) { g_rowptr[i] = excl; g_wpos[i] = excl; }
    __syncthreads();
    if (tid == 1023) carry = excl + v;
    __syncthreads();
  }
  if (threadIdx.x == 0) g_rowptr[NN] = carry;
}

__global__ void k_scatter(const int* __restrict__ ei) {
  int i = blockIdx.x * blockDim.x + threadIdx.x;
  if (i >= EE) return;
  int d = ei[EE + i];
  int p = atomicAdd(&g_wpos[d], 1);
  g_col[p] = ei[i];
}

// ---------------- GEMM1: h1 = x @ W1 (fp16 out) ; fused attn scores ----------------
__global__ __launch_bounds__(256) void k_gemm1(const float* __restrict__ x,
                                               const float* __restrict__ W1,
                                               const float* __restrict__ as1,
                                               const float* __restrict__ ad1) {
  __shared__ float Ws[FF * HC];    // 32 KB
  __shared__ float Xs[64][33];
  int tid = threadIdx.x;
  for (int i = tid; i < FF * HC / 4; i += 256) ((float4*)Ws)[i] = ((const float4*)W1)[i];
  int m0 = blockIdx.x * 64;
  for (int i = tid; i < 512; i += 256) {
    int r = i >> 3, c4 = i & 7;
    float4 v = make_float4(0.f, 0.f, 0.f, 0.f);
    if (m0 + r < NN) v = ((const float4*)(x + (size_t)(m0 + r) * FF))[c4];
    Xs[r][c4 * 4 + 0] = v.x; Xs[r][c4 * 4 + 1] = v.y;
    Xs[r][c4 * 4 + 2] = v.z; Xs[r][c4 * 4 + 3] = v.w;
  }
  __syncthreads();
  int tx = tid & 31, ty = tid >> 5;
  float acc[8][8] = {};
#pragma unroll
  for (int k = 0; k < FF; k++) {
    float a[8];
#pragma unroll
    for (int i = 0; i < 8; i++) a[i] = Xs[ty * 8 + i][k];
    float4 b0 = *(const float4*)(Ws + k * HC + tx * 8);
    float4 b1v = *(const float4*)(Ws + k * HC + tx * 8 + 4);
    float b[8] = {b0.x, b0.y, b0.z, b0.w, b1v.x, b1v.y, b1v.z, b1v.w};
#pragma unroll
    for (int i = 0; i < 8; i++)
#pragma unroll
      for (int j = 0; j < 8; j++) acc[i][j] += a[i] * b[j];
  }
  float asr[8], adr[8];
#pragma unroll
  for (int j = 0; j < 8; j++) { asr[j] = __ldg(as1 + tx * 8 + j); adr[j] = __ldg(ad1 + tx * 8 + j); }
#pragma unroll
  for (int i = 0; i < 8; i++) {
    int row = m0 + ty * 8 + i;
    float ps = 0.f, pd = 0.f;
#pragma unroll
    for (int j = 0; j < 8; j++) { ps += acc[i][j] * asr[j]; pd += acc[i][j] * adr[j]; }
#pragma unroll
    for (int o = 4; o; o >>= 1) {
      ps += __shfl_down_sync(0xffffffffu, ps, o, 8);
      pd += __shfl_down_sync(0xffffffffu, pd, o, 8);
    }
    if (row < NN) {
      if ((tx & 7) == 0) {
        ((float*)&g_ssrc1[row])[tx >> 3] = ps;
        ((float*)&g_sdst1[row])[tx >> 3] = pd;
      }
      uint4 u;
      ((__half2*)&u)[0] = __floats2half2_rn(acc[i][0], acc[i][1]);
      ((__half2*)&u)[1] = __floats2half2_rn(acc[i][2], acc[i][3]);
      ((__half2*)&u)[2] = __floats2half2_rn(acc[i][4], acc[i][5]);
      ((__half2*)&u)[3] = __floats2half2_rn(acc[i][6], acc[i][7]);
      ((uint4*)(g_h1 + (size_t)row * HC))[tx] = u;
    }
  }
}

// ---------------- GAT1: single-pass softmax-aggregate, warp per dst node ----------------
// Each lane owns 8 consecutive channels (all in head lane>>3).
__global__ __launch_bounds__(256) void k_gat1(const float* __restrict__ b1) {
  __shared__ int    sIdx[8][32];
  __shared__ float4 sE[8][32];
  int wslot = threadIdx.x >> 5;
  int gw = (blockIdx.x * blockDim.x + threadIdx.x) >> 5;
  if (gw >= NN) return;
  int lane = threadIdx.x & 31;
  int base = g_rowptr[gw];
  int deg = g_rowptr[gw + 1] - base;           // +1 virtual self loop at index deg
  float4 sd = g_sdst1[gw];
  int head = lane >> 3;
  float acc[8] = {0, 0, 0, 0, 0, 0, 0, 0};
  float s0 = 0, s1 = 0, s2 = 0, s3 = 0;

  for (int c0 = 0; c0 <= deg; c0 += 32) {
    int i = c0 + lane;
    float4 e4 = {0, 0, 0, 0};
    int s = gw;
    if (i <= deg) {
      s = (i < deg) ? g_col[base + i] : gw;
      float4 ss = g_ssrc1[s];
      e4.x = __expf(lrelu(ss.x + sd.x));
      e4.y = __expf(lrelu(ss.y + sd.y));
      e4.z = __expf(lrelu(ss.z + sd.z));
      e4.w = __expf(lrelu(ss.w + sd.w));
      s0 += e4.x; s1 += e4.y; s2 += e4.z; s3 += e4.w;
    }
    sIdx[wslot][lane] = s;
    sE[wslot][lane] = e4;
    __syncwarp();
    int cnt = min(32, deg + 1 - c0);
#pragma unroll 4
    for (int j = 0; j < cnt; j++) {
      int sj = sIdx[wslot][j];
      float w = ((const float*)&sE[wslot][j])[head];
      uint4 raw = ((const uint4*)(g_h1 + (size_t)sj * HC))[lane];
      const __half2* ph = (const __half2*)&raw;
      float2 f0 = __half22float2(ph[0]);
      float2 f1 = __half22float2(ph[1]);
      float2 f2 = __half22float2(ph[2]);
      float2 f3 = __half22float2(ph[3]);
      acc[0] += w * f0.x; acc[1] += w * f0.y;
      acc[2] += w * f1.x; acc[3] += w * f1.y;
      acc[4] += w * f2.x; acc[5] += w * f2.y;
      acc[6] += w * f3.x; acc[7] += w * f3.y;
    }
    __syncwarp();
  }
  s0 = warpSum(s0); s1 = warpSum(s1); s2 = warpSum(s2); s3 = warpSum(s3);
  float sums[4] = {s0, s1, s2, s3};
  float inv = 1.f / sums[head];
  float4 bb0 = *(const float4*)(b1 + lane * 8);
  float4 bb1 = *(const float4*)(b1 + lane * 8 + 4);
  float bbs[8] = {bb0.x, bb0.y, bb0.z, bb0.w, bb1.x, bb1.y, bb1.z, bb1.w};
  uint4 u;
  float o[8];
#pragma unroll
  for (int j = 0; j < 8; j++) o[j] = fmaxf(acc[j] * inv + bbs[j], 0.f);
  ((__half2*)&u)[0] = __floats2half2_rn(o[0], o[1]);
  ((__half2*)&u)[1] = __floats2half2_rn(o[2], o[3]);
  ((__half2*)&u)[2] = __floats2half2_rn(o[4], o[5]);
  ((__half2*)&u)[3] = __floats2half2_rn(o[6], o[7]);
  ((uint4*)(g_out1 + (size_t)gw * HC))[lane] = u;
}

// ---------------- GEMM2: h2 = out1(fp16) @ W2 ; fused GAT2 scores ----------------
__global__ __launch_bounds__(256) void k_gemm2(const float* __restrict__ W2,
                                               const float* __restrict__ as2,
                                               const float* __restrict__ ad2) {
  __shared__ float As[64][33];
  __shared__ float Bs[32][64];
  int tid = threadIdx.x;
  int tx = tid & 15, ty = tid >> 4;
  int m0 = blockIdx.x * 64;
  float acc[4][4] = {};
  for (int k0 = 0; k0 < HC; k0 += 32) {
    for (int i = tid; i < 64 * 16; i += 256) {   // 16 half2 per row
      int r = i >> 4, c2 = i & 15;
      int row = m0 + r;
      float2 v = {0.f, 0.f};
      if (row < NN) v = __half22float2(((const __half2*)(g_out1 + (size_t)row * HC + k0))[c2]);
      As[r][c2 * 2] = v.x;
      As[r][c2 * 2 + 1] = v.y;
    }
    for (int i = tid; i < 32 * 64; i += 256) {
      int r = i >> 6, c = i & 63;
      Bs[r][c] = W2[(k0 + r) * 64 + c];
    }
    __syncthreads();
#pragma unroll
    for (int k = 0; k < 32; k++) {
      float a[4], b[4];
#pragma unroll
      for (int i = 0; i < 4; i++) a[i] = As[ty * 4 + i][k];
#pragma unroll
      for (int j = 0; j < 4; j++) b[j] = Bs[k][tx * 4 + j];
#pragma unroll
      for (int i = 0; i < 4; i++)
#pragma unroll
        for (int j = 0; j < 4; j++) acc[i][j] += a[i] * b[j];
    }
    __syncthreads();
  }
  float asr[4], adr[4];
#pragma unroll
  for (int j = 0; j < 4; j++) { asr[j] = __ldg(as2 + tx * 4 + j); adr[j] = __ldg(ad2 + tx * 4 + j); }
#pragma unroll
  for (int i = 0; i < 4; i++) {
    int row = m0 + ty * 4 + i;
    float ps = 0.f, pd = 0.f;
#pragma unroll
    for (int j = 0; j < 4; j++) { ps += acc[i][j] * asr[j]; pd += acc[i][j] * adr[j]; }
#pragma unroll
    for (int o = 8; o; o >>= 1) {
      ps += __shfl_down_sync(0xffffffffu, ps, o, 16);
      pd += __shfl_down_sync(0xffffffffu, pd, o, 16);
    }
    if (row < NN) {
      if (tx == 0) { g_ssrc2[row] = ps; g_sdst2[row] = pd; }
      uint2 u;
      ((__half2*)&u)[0] = __floats2half2_rn(acc[i][0], acc[i][1]);
      ((__half2*)&u)[1] = __floats2half2_rn(acc[i][2], acc[i][3]);
      ((uint2*)(g_h2 + (size_t)row * 64))[tx] = u;
    }
  }
}

// ---------------- GAT2: single-pass aggregate + mean-pool scatter ----------------
__global__ __launch_bounds__(256) void k_gat2(const float* __restrict__ b2,
                                              const int* __restrict__ batch, int t) {
  __shared__ int   sIdx[8][32];
  __shared__ float sEs[8][32];
  int wslot = threadIdx.x >> 5;
  int gw = (blockIdx.x * blockDim.x + threadIdx.x) >> 5;
  if (gw >= NN) return;
  int lane = threadIdx.x & 31;
  int base = g_rowptr[gw];
  int deg = g_rowptr[gw + 1] - base;
  float sd = g_sdst2[gw];
  float2 acc = {0, 0};
  float sum = 0.f;

  for (int c0 = 0; c0 <= deg; c0 += 32) {
    int i = c0 + lane;
    float e = 0.f;
    int s = gw;
    if (i <= deg) {
      s = (i < deg) ? g_col[base + i] : gw;
      e = __expf(lrelu(g_ssrc2[s] + sd));
      sum += e;
    }
    sIdx[wslot][lane] = s;
    sEs[wslot][lane] = e;
    __syncwarp();
    int cnt = min(32, deg + 1 - c0);
#pragma unroll 4
    for (int j = 0; j < cnt; j++) {
      int sj = sIdx[wslot][j];
      float ej = sEs[wslot][j];
      float2 v = __half22float2(((const __half2*)(g_h2 + (size_t)sj * 64))[lane]);
      acc.x += ej * v.x;
      acc.y += ej * v.y;
    }
    __syncwarp();
  }
  sum = warpSum(sum);
  float inv = 1.f / sum;
  int b = batch[gw];
  float v0 = acc.x * inv + b2[lane * 2];
  float v1 = acc.y * inv + b2[lane * 2 + 1];
  atomicAdd(&g_pooled[b * (SS * DD) + t * DD + lane * 2], v0);
  atomicAdd(&g_pooled[b * (SS * DD) + t * DD + lane * 2 + 1], v1);
}

// ---------------- final: MHA + residual + LN + temporal mean + proj ----------------
__global__ __launch_bounds__(256) void k_final(const float* __restrict__ ipw, const float* __restrict__ ipb,
                                               const float* __restrict__ opw, const float* __restrict__ opb,
                                               const float* __restrict__ lng, const float* __restrict__ lnb,
                                               const float* __restrict__ pw,  const float* __restrict__ pb,
                                               float* __restrict__ out) {
  __shared__ float sx[96 * 64];
  __shared__ float sym[16 * 64];
  __shared__ float sinv[16];
  int tid = threadIdx.x;
  if (tid < 16) {
    int c = g_batchcnt[tid];
    sinv[tid] = 1.f / (c > 0 ? (float)c : 1.f);
  }
  for (int i = tid; i < 16 * 64; i += 256) sym[i] = 0.f;
  __syncthreads();
  for (int i = tid; i < 96 * 64; i += 256) {
    int row = i >> 6;
    sx[i] = g_pooled[i] * sinv[row / 6];
  }
  __syncthreads();
  for (int i = tid; i < 96 * 192; i += 256) {
    int row = i / 192, j = i - row * 192;
    float acc = ipb[j];
    const float* xr = &sx[row * 64];
    const float* wr = &ipw[j * 64];
    for (int c = 0; c < 64; c++) acc += xr[c] * wr[c];
    g_qkv[i] = acc;
  }
  __syncthreads();
  if (tid < 64) {
    int b = tid >> 2, h = tid & 3;
    for (int s1 = 0; s1 < 6; s1++) {
      float sc[6];
      float mx = -1e30f;
      const float* qr = &g_qkv[(b * 6 + s1) * 192 + h * 16];
      for (int s2 = 0; s2 < 6; s2++) {
        const float* kr = &g_qkv[(b * 6 + s2) * 192 + 64 + h * 16];
        float d = 0.f;
        for (int u = 0; u < 16; u++) d += qr[u] * kr[u];
        sc[s2] = d * 0.25f;
        mx = fmaxf(mx, sc[s2]);
      }
      float ssum = 0.f;
      for (int s2 = 0; s2 < 6; s2++) { sc[s2] = __expf(sc[s2] - mx); ssum += sc[s2]; }
      float invs = 1.f / ssum;
      float o[16];
      for (int u = 0; u < 16; u++) o[u] = 0.f;
      for (int s2 = 0; s2 < 6; s2++) {
        float w = sc[s2] * invs;
        const float* vr = &g_qkv[(b * 6 + s2) * 192 + 128 + h * 16];
        for (int u = 0; u < 16; u++) o[u] += w * vr[u];
      }
      float* orow = &g_go[(b * 6 + s1) * 64 + h * 16];
      for (int u = 0; u < 16; u++) orow[u] = o[u];
    }
  }
  __syncthreads();
  int wid = tid >> 5, lane = tid & 31;
  for (int row = wid; row < 96; row += 8) {
    const float* orow = &g_go[row * 64];
    float y0 = opb[lane], y1 = opb[lane + 32];
    for (int c = 0; c < 64; c++) {
      float ov = orow[c];
      y0 += ov * opw[lane * 64 + c];
      y1 += ov * opw[(lane + 32) * 64 + c];
    }
    y0 += sx[row * 64 + lane];
    y1 += sx[row * 64 + lane + 32];
    float s = warpSum(y0 + y1);
    float mu = s * (1.f / 64.f);
    float d0 = y0 - mu, d1 = y1 - mu;
    float vs = warpSum(d0 * d0 + d1 * d1);
    float var = vs * (1.f / 64.f);
    float r = rsqrtf(var + 1e-5f);
    float z0 = d0 * r * lng[lane] + lnb[lane];
    float z1 = d1 * r * lng[lane + 32] + lnb[lane + 32];
    int b = row / 6;
    atomicAdd(&sym[b * 64 + lane], z0 * (1.f / 6.f));
    atomicAdd(&sym[b * 64 + lane + 32], z1 * (1.f / 6.f));
  }
  __syncthreads();
  for (int i = tid; i < 16 * 64; i += 256) {
    int b = i >> 6, j = i & 63;
    float acc = pb[j];
    const float* yr = &sym[b * 64];
    const float* wr = &pw[j * 64];
    for (int c = 0; c < 64; c++) acc += yr[c] * wr[c];
    out[i] = acc;
  }
}

// ---------------- launch ----------------
extern "C" void kernel_launch(void* const* d_in, const int* in_sizes, int n_in,
                              void* d_out, int out_size) {
  const float* x_seq = (const float*)d_in[0];
  const int*   ei    = (const int*)d_in[1];
  const int*   batch = (const int*)d_in[2];
  const float* W1    = (const float*)d_in[3];
  const float* as1   = (const float*)d_in[4];
  const float* ad1   = (const float*)d_in[5];
  const float* b1    = (const float*)d_in[6];
  const float* W2    = (const float*)d_in[7];
  const float* as2   = (const float*)d_in[8];
  const float* ad2   = (const float*)d_in[9];
  const float* b2    = (const float*)d_in[10];
  const float* ipw   = (const float*)d_in[11];
  const float* ipb   = (const float*)d_in[12];
  const float* opw   = (const float*)d_in[13];
  const float* opb   = (const float*)d_in[14];
  const float* lng   = (const float*)d_in[15];
  const float* lnb   = (const float*)d_in[16];
  const float* pw    = (const float*)d_in[17];
  const float* pb    = (const float*)d_in[18];
  float* out = (float*)d_out;

  k_init<<<(NN + 255) / 256, 256>>>();
  k_hist<<<(EE + 255) / 256, 256>>>(ei, batch);
  k_scan<<<1, 1024>>>();
  k_scatter<<<(EE + 255) / 256, 256>>>(ei);

  for (int t = 0; t < SS; t++) {
    k_gemm1<<<(NN + 63) / 64, 256>>>(x_seq + (size_t)t * NN * FF, W1, as1, ad1);
    k_gat1<<<(NN * 32 + 255) / 256, 256>>>(b1);
    k_gemm2<<<(NN + 63) / 64, 256>>>(W2, as2, ad2);
    k_gat2<<<(NN * 32 + 255) / 256, 256>>>(b2, batch, t);
  }
  k_final<<<1, 256>>>(ipw, ipb, opw, opb, lng, lnb, pw, pb, out);
}

// round 4
// speedup vs baseline: 2.6531x; 2.2362x over previous
#include <cuda_runtime.h>
#include <cuda_fp16.h>
#include <cstdint>

#define NN 20000
#define EE 640000
#define FF 32
#define HH 4
#define CC 64
#define SS 6
#define BB 16
#define DD 64
#define HC 256   // H*C

// ---------------- device scratch (double-buffered by timestep parity) ----------------
__device__ int    g_counts[NN];
__device__ int    g_rowptr[NN + 1];
__device__ int    g_wpos[NN];
__device__ int    g_col[EE];
__device__ int    g_batchcnt[BB];
__device__ __half g_h1[2][(size_t)NN * HC];
__device__ __half g_out1[2][(size_t)NN * HC];
__device__ float4 g_ssrc1[2][NN];
__device__ float4 g_sdst1[2][NN];
__device__ __half g_h2[2][(size_t)NN * CC];
__device__ float  g_ssrc2[2][NN];
__device__ float  g_sdst2[2][NN];
__device__ float  g_pooled[BB * SS * DD];
__device__ float  g_sx[96 * 64];
__device__ float  g_qkv[96 * 192];

__device__ __forceinline__ float lrelu(float x) { return x > 0.f ? x : 0.2f * x; }
__device__ __forceinline__ float warpSum(float v) {
#pragma unroll
  for (int o = 16; o; o >>= 1) v += __shfl_xor_sync(0xffffffffu, v, o);
  return v;
}

// ---------------- CSR build ----------------
__global__ void k_hist(const int* __restrict__ ei, const int* __restrict__ batch) {
  int i = blockIdx.x * blockDim.x + threadIdx.x;
  if (i < EE) atomicAdd(&g_counts[ei[EE + i]], 1);
  if (i < NN) atomicAdd(&g_batchcnt[batch[i]], 1);
}

__global__ void k_scan() {
  __shared__ int wsum[32];
  __shared__ int carry;
  int tid = threadIdx.x, lane = tid & 31, wid = tid >> 5;
  if (tid == 0) carry = 0;
  __syncthreads();
  for (int base = 0; base < NN; base += 1024) {
    int i = base + tid;
    int v = (i < NN) ? g_counts[i] : 0;
    int incl = v;
#pragma unroll
    for (int o = 1; o < 32; o <<= 1) { int u = __shfl_up_sync(0xffffffffu, incl, o); if (lane >= o) incl += u; }
    if (lane == 31) wsum[wid] = incl;
    __syncthreads();
    if (wid == 0) {
      int ws = wsum[lane];
      int wi = ws;
#pragma unroll
      for (int o = 1; o < 32; o <<= 1) { int u = __shfl_up_sync(0xffffffffu, wi, o); if (lane >= o) wi += u; }
      wsum[lane] = wi - ws;
    }
    __syncthreads();
    int excl = incl - v + wsum[wid] + carry;
    if (i < NN) { g_rowptr[i] = excl; g_wpos[i] = excl; }
    __syncthreads();
    if (tid == 1023) carry = excl + v;
    __syncthreads();
  }
  if (threadIdx.x == 0) g_rowptr[NN] = carry;
}

__global__ void k_scatter(const int* __restrict__ ei) {
  int i = blockIdx.x * blockDim.x + threadIdx.x;
  if (i >= EE) return;
  int d = ei[EE + i];
  int p = atomicAdd(&g_wpos[d], 1);
  g_col[p] = ei[i];
}

// ---------------- GEMM1: h1 = x @ W1 (fp16 out) ; fused attn scores ----------------
__global__ __launch_bounds__(256) void k_gemm1(const float* __restrict__ x,
                                               const float* __restrict__ W1,
                                               const float* __restrict__ as1,
                                               const float* __restrict__ ad1, int p) {
  __shared__ float Ws[FF * HC];
  __shared__ float Xs[64][33];
  int tid = threadIdx.x;
  for (int i = tid; i < FF * HC / 4; i += 256) ((float4*)Ws)[i] = ((const float4*)W1)[i];
  int m0 = blockIdx.x * 64;
  for (int i = tid; i < 512; i += 256) {
    int r = i >> 3, c4 = i & 7;
    float4 v = make_float4(0.f, 0.f, 0.f, 0.f);
    if (m0 + r < NN) v = ((const float4*)(x + (size_t)(m0 + r) * FF))[c4];
    Xs[r][c4 * 4 + 0] = v.x; Xs[r][c4 * 4 + 1] = v.y;
    Xs[r][c4 * 4 + 2] = v.z; Xs[r][c4 * 4 + 3] = v.w;
  }
  __syncthreads();
  int tx = tid & 31, ty = tid >> 5;
  float acc[8][8] = {};
#pragma unroll
  for (int k = 0; k < FF; k++) {
    float a[8];
#pragma unroll
    for (int i = 0; i < 8; i++) a[i] = Xs[ty * 8 + i][k];
    float4 b0 = *(const float4*)(Ws + k * HC + tx * 8);
    float4 b1v = *(const float4*)(Ws + k * HC + tx * 8 + 4);
    float b[8] = {b0.x, b0.y, b0.z, b0.w, b1v.x, b1v.y, b1v.z, b1v.w};
#pragma unroll
    for (int i = 0; i < 8; i++)
#pragma unroll
      for (int j = 0; j < 8; j++) acc[i][j] += a[i] * b[j];
  }
  float asr[8], adr[8];
#pragma unroll
  for (int j = 0; j < 8; j++) { asr[j] = __ldg(as1 + tx * 8 + j); adr[j] = __ldg(ad1 + tx * 8 + j); }
#pragma unroll
  for (int i = 0; i < 8; i++) {
    int row = m0 + ty * 8 + i;
    float ps = 0.f, pd = 0.f;
#pragma unroll
    for (int j = 0; j < 8; j++) { ps += acc[i][j] * asr[j]; pd += acc[i][j] * adr[j]; }
#pragma unroll
    for (int o = 4; o; o >>= 1) {
      ps += __shfl_down_sync(0xffffffffu, ps, o, 8);
      pd += __shfl_down_sync(0xffffffffu, pd, o, 8);
    }
    if (row < NN) {
      if ((tx & 7) == 0) {
        ((float*)&g_ssrc1[p][row])[tx >> 3] = ps;
        ((float*)&g_sdst1[p][row])[tx >> 3] = pd;
      }
      uint4 u;
      ((__half2*)&u)[0] = __floats2half2_rn(acc[i][0], acc[i][1]);
      ((__half2*)&u)[1] = __floats2half2_rn(acc[i][2], acc[i][3]);
      ((__half2*)&u)[2] = __floats2half2_rn(acc[i][4], acc[i][5]);
      ((__half2*)&u)[3] = __floats2half2_rn(acc[i][6], acc[i][7]);
      ((uint4*)(g_h1[p] + (size_t)row * HC))[tx] = u;
    }
  }
}

// ---------------- GAT1: single-pass softmax-aggregate, warp per dst node ----------------
__global__ __launch_bounds__(256) void k_gat1(const float* __restrict__ b1, int p) {
  __shared__ int    sIdx[8][32];
  __shared__ float4 sE[8][32];
  int wslot = threadIdx.x >> 5;
  int gw = (blockIdx.x * blockDim.x + threadIdx.x) >> 5;
  if (gw >= NN) return;
  int lane = threadIdx.x & 31;
  int base = g_rowptr[gw];
  int deg = g_rowptr[gw + 1] - base;
  float4 sd = g_sdst1[p][gw];
  int head = lane >> 3;
  const __half* h1p = g_h1[p];
  float acc[8] = {0, 0, 0, 0, 0, 0, 0, 0};
  float s0 = 0, s1 = 0, s2 = 0, s3 = 0;

  for (int c0 = 0; c0 <= deg; c0 += 32) {
    int i = c0 + lane;
    float4 e4 = {0, 0, 0, 0};
    int s = gw;
    if (i <= deg) {
      s = (i < deg) ? g_col[base + i] : gw;
      float4 ss = g_ssrc1[p][s];
      e4.x = __expf(lrelu(ss.x + sd.x));
      e4.y = __expf(lrelu(ss.y + sd.y));
      e4.z = __expf(lrelu(ss.z + sd.z));
      e4.w = __expf(lrelu(ss.w + sd.w));
      s0 += e4.x; s1 += e4.y; s2 += e4.z; s3 += e4.w;
    }
    sIdx[wslot][lane] = s;
    sE[wslot][lane] = e4;
    __syncwarp();
    int cnt = min(32, deg + 1 - c0);
#pragma unroll 4
    for (int j = 0; j < cnt; j++) {
      int sj = sIdx[wslot][j];
      float w = ((const float*)&sE[wslot][j])[head];
      uint4 raw = ((const uint4*)(h1p + (size_t)sj * HC))[lane];
      const __half2* ph = (const __half2*)&raw;
      float2 f0 = __half22float2(ph[0]);
      float2 f1 = __half22float2(ph[1]);
      float2 f2 = __half22float2(ph[2]);
      float2 f3 = __half22float2(ph[3]);
      acc[0] += w * f0.x; acc[1] += w * f0.y;
      acc[2] += w * f1.x; acc[3] += w * f1.y;
      acc[4] += w * f2.x; acc[5] += w * f2.y;
      acc[6] += w * f3.x; acc[7] += w * f3.y;
    }
    __syncwarp();
  }
  s0 = warpSum(s0); s1 = warpSum(s1); s2 = warpSum(s2); s3 = warpSum(s3);
  float sums[4] = {s0, s1, s2, s3};
  float inv = 1.f / sums[head];
  float4 bb0 = *(const float4*)(b1 + lane * 8);
  float4 bb1 = *(const float4*)(b1 + lane * 8 + 4);
  float bbs[8] = {bb0.x, bb0.y, bb0.z, bb0.w, bb1.x, bb1.y, bb1.z, bb1.w};
  uint4 u;
  float o[8];
#pragma unroll
  for (int j = 0; j < 8; j++) o[j] = fmaxf(acc[j] * inv + bbs[j], 0.f);
  ((__half2*)&u)[0] = __floats2half2_rn(o[0], o[1]);
  ((__half2*)&u)[1] = __floats2half2_rn(o[2], o[3]);
  ((__half2*)&u)[2] = __floats2half2_rn(o[4], o[5]);
  ((__half2*)&u)[3] = __floats2half2_rn(o[6], o[7]);
  ((uint4*)(g_out1[p] + (size_t)gw * HC))[lane] = u;
}

// ---------------- GEMM2: h2 = out1(fp16) @ W2 ; fused GAT2 scores ----------------
__global__ __launch_bounds__(256) void k_gemm2(const float* __restrict__ W2,
                                               const float* __restrict__ as2,
                                               const float* __restrict__ ad2, int p) {
  __shared__ float As[64][33];
  __shared__ float Bs[32][64];
  int tid = threadIdx.x;
  int tx = tid & 15, ty = tid >> 4;
  int m0 = blockIdx.x * 64;
  float acc[4][4] = {};
  const __half* o1p = g_out1[p];
  for (int k0 = 0; k0 < HC; k0 += 32) {
    for (int i = tid; i < 64 * 16; i += 256) {
      int r = i >> 4, c2 = i & 15;
      int row = m0 + r;
      float2 v = {0.f, 0.f};
      if (row < NN) v = __half22float2(((const __half2*)(o1p + (size_t)row * HC + k0))[c2]);
      As[r][c2 * 2] = v.x;
      As[r][c2 * 2 + 1] = v.y;
    }
    for (int i = tid; i < 32 * 64; i += 256) {
      int r = i >> 6, c = i & 63;
      Bs[r][c] = W2[(k0 + r) * 64 + c];
    }
    __syncthreads();
#pragma unroll
    for (int k = 0; k < 32; k++) {
      float a[4], b[4];
#pragma unroll
      for (int i = 0; i < 4; i++) a[i] = As[ty * 4 + i][k];
#pragma unroll
      for (int j = 0; j < 4; j++) b[j] = Bs[k][tx * 4 + j];
#pragma unroll
      for (int i = 0; i < 4; i++)
#pragma unroll
        for (int j = 0; j < 4; j++) acc[i][j] += a[i] * b[j];
    }
    __syncthreads();
  }
  float asr[4], adr[4];
#pragma unroll
  for (int j = 0; j < 4; j++) { asr[j] = __ldg(as2 + tx * 4 + j); adr[j] = __ldg(ad2 + tx * 4 + j); }
#pragma unroll
  for (int i = 0; i < 4; i++) {
    int row = m0 + ty * 4 + i;
    float ps = 0.f, pd = 0.f;
#pragma unroll
    for (int j = 0; j < 4; j++) { ps += acc[i][j] * asr[j]; pd += acc[i][j] * adr[j]; }
#pragma unroll
    for (int o = 8; o; o >>= 1) {
      ps += __shfl_down_sync(0xffffffffu, ps, o, 16);
      pd += __shfl_down_sync(0xffffffffu, pd, o, 16);
    }
    if (row < NN) {
      if (tx == 0) { g_ssrc2[p][row] = ps; g_sdst2[p][row] = pd; }
      uint2 u;
      ((__half2*)&u)[0] = __floats2half2_rn(acc[i][0], acc[i][1]);
      ((__half2*)&u)[1] = __floats2half2_rn(acc[i][2], acc[i][3]);
      ((uint2*)(g_h2[p] + (size_t)row * 64))[tx] = u;
    }
  }
}

// ---------------- GAT2: single-pass aggregate + mean-pool scatter ----------------
__global__ __launch_bounds__(256) void k_gat2(const float* __restrict__ b2,
                                              const int* __restrict__ batch, int t, int p) {
  __shared__ int   sIdx[8][32];
  __shared__ float sEs[8][32];
  int wslot = threadIdx.x >> 5;
  int gw = (blockIdx.x * blockDim.x + threadIdx.x) >> 5;
  if (gw >= NN) return;
  int lane = threadIdx.x & 31;
  int base = g_rowptr[gw];
  int deg = g_rowptr[gw + 1] - base;
  float sd = g_sdst2[p][gw];
  const __half* h2p = g_h2[p];
  const float* ss2 = g_ssrc2[p];
  float2 acc = {0, 0};
  float sum = 0.f;

  for (int c0 = 0; c0 <= deg; c0 += 32) {
    int i = c0 + lane;
    float e = 0.f;
    int s = gw;
    if (i <= deg) {
      s = (i < deg) ? g_col[base + i] : gw;
      e = __expf(lrelu(ss2[s] + sd));
      sum += e;
    }
    sIdx[wslot][lane] = s;
    sEs[wslot][lane] = e;
    __syncwarp();
    int cnt = min(32, deg + 1 - c0);
#pragma unroll 4
    for (int j = 0; j < cnt; j++) {
      int sj = sIdx[wslot][j];
      float ej = sEs[wslot][j];
      float2 v = __half22float2(((const __half2*)(h2p + (size_t)sj * 64))[lane]);
      acc.x += ej * v.x;
      acc.y += ej * v.y;
    }
    __syncwarp();
  }
  sum = warpSum(sum);
  float inv = 1.f / sum;
  int b = batch[gw];
  float v0 = acc.x * inv + b2[lane * 2];
  float v1 = acc.y * inv + b2[lane * 2 + 1];
  atomicAdd(&g_pooled[b * (SS * DD) + t * DD + lane * 2], v0);
  atomicAdd(&g_pooled[b * (SS * DD) + t * DD + lane * 2 + 1], v1);
}

// ---------------- final A: mean-pool normalize + qkv projection (96 blocks) ----------------
__global__ __launch_bounds__(192) void k_final_a(const float* __restrict__ ipw,
                                                 const float* __restrict__ ipb) {
  __shared__ float xr[64];
  int r = blockIdx.x;
  int tid = threadIdx.x;
  if (tid < 64) {
    int c = g_batchcnt[r / 6];
    float inv = 1.f / (c > 0 ? (float)c : 1.f);
    float v = g_pooled[r * 64 + tid] * inv;
    xr[tid] = v;
    g_sx[r * 64 + tid] = v;
  }
  __syncthreads();
  float acc = ipb[tid];
  const float* wr = &ipw[tid * 64];
#pragma unroll 8
  for (int c = 0; c < 64; c++) acc += xr[c] * wr[c];
  g_qkv[r * 192 + tid] = acc;
}

// ---------------- final B: attention + out_proj + LN + temporal mean + proj (16 blocks) ----------------
__global__ __launch_bounds__(128) void k_final_b(const float* __restrict__ opw, const float* __restrict__ opb,
                                                 const float* __restrict__ lng, const float* __restrict__ lnb,
                                                 const float* __restrict__ pw,  const float* __restrict__ pb,
                                                 float* __restrict__ out) {
  __shared__ float q[6 * 192];
  __shared__ float att[6 * 64];
  __shared__ float ym[6 * 64];
  __shared__ float zacc[64];
  int b = blockIdx.x;
  int tid = threadIdx.x;
  for (int i = tid; i < 6 * 192; i += 128) q[i] = g_qkv[b * 6 * 192 + i];
  if (tid < 64) zacc[tid] = 0.f;
  __syncthreads();
  if (tid < 24) {
    int s1 = tid >> 2, h = tid & 3;
    float sc[6];
    float mx = -1e30f;
    const float* qr = &q[s1 * 192 + h * 16];
    for (int s2 = 0; s2 < 6; s2++) {
      const float* kr = &q[s2 * 192 + 64 + h * 16];
      float d = 0.f;
#pragma unroll
      for (int u = 0; u < 16; u++) d += qr[u] * kr[u];
      sc[s2] = d * 0.25f;
      mx = fmaxf(mx, sc[s2]);
    }
    float ssum = 0.f;
    for (int s2 = 0; s2 < 6; s2++) { sc[s2] = __expf(sc[s2] - mx); ssum += sc[s2]; }
    float invs = 1.f / ssum;
    float o[16];
#pragma unroll
    for (int u = 0; u < 16; u++) o[u] = 0.f;
    for (int s2 = 0; s2 < 6; s2++) {
      float w = sc[s2] * invs;
      const float* vr = &q[s2 * 192 + 128 + h * 16];
#pragma unroll
      for (int u = 0; u < 16; u++) o[u] += w * vr[u];
    }
    for (int u = 0; u < 16; u++) att[s1 * 64 + h * 16 + u] = o[u];
  }
  __syncthreads();
  for (int i = tid; i < 6 * 64; i += 128) {
    int r = i >> 6, c = i & 63;
    float acc = opb[c];
    const float* ar = &att[r * 64];
    const float* wr = &opw[c * 64];
#pragma unroll 8
    for (int k = 0; k < 64; k++) acc += ar[k] * wr[k];
    ym[i] = acc + g_sx[(b * 6 + r) * 64 + c];
  }
  __syncthreads();
  int wid = tid >> 5, lane = tid & 31;
  for (int row = wid; row < 6; row += 4) {
    float y0 = ym[row * 64 + lane];
    float y1 = ym[row * 64 + 32 + lane];
    float s = warpSum(y0 + y1);
    float mu = s * (1.f / 64.f);
    float d0 = y0 - mu, d1 = y1 - mu;
    float vs = warpSum(d0 * d0 + d1 * d1);
    float var = vs * (1.f / 64.f);
    float r = rsqrtf(var + 1e-5f);
    float z0 = d0 * r * lng[lane] + lnb[lane];
    float z1 = d1 * r * lng[lane + 32] + lnb[lane + 32];
    atomicAdd(&zacc[lane], z0 * (1.f / 6.f));
    atomicAdd(&zacc[lane + 32], z1 * (1.f / 6.f));
  }
  __syncthreads();
  if (tid < 64) {
    float acc = pb[tid];
    const float* wr = &pw[tid * 64];
#pragma unroll 8
    for (int k = 0; k < 64; k++) acc += zacc[k] * wr[k];
    out[b * 64 + tid] = acc;
  }
}

// ---------------- launch ----------------
extern "C" void kernel_launch(void* const* d_in, const int* in_sizes, int n_in,
                              void* d_out, int out_size) {
  const float* x_seq = (const float*)d_in[0];
  const int*   ei    = (const int*)d_in[1];
  const int*   batch = (const int*)d_in[2];
  const float* W1    = (const float*)d_in[3];
  const float* as1   = (const float*)d_in[4];
  const float* ad1   = (const float*)d_in[5];
  const float* b1    = (const float*)d_in[6];
  const float* W2    = (const float*)d_in[7];
  const float* as2   = (const float*)d_in[8];
  const float* ad2   = (const float*)d_in[9];
  const float* b2    = (const float*)d_in[10];
  const float* ipw   = (const float*)d_in[11];
  const float* ipb   = (const float*)d_in[12];
  const float* opw   = (const float*)d_in[13];
  const float* opb   = (const float*)d_in[14];
  const float* lng   = (const float*)d_in[15];
  const float* lnb   = (const float*)d_in[16];
  const float* pw    = (const float*)d_in[17];
  const float* pb    = (const float*)d_in[18];
  float* out = (float*)d_out;

  // One-time handles (created on the uncaptured correctness call; reused during capture).
  static cudaStream_t st[2] = {nullptr, nullptr};
  static cudaEvent_t ev_root = nullptr, ev_d0 = nullptr, ev_d1 = nullptr;
  static void *a_counts = nullptr, *a_batchcnt = nullptr, *a_pooled = nullptr;
  if (ev_root == nullptr) {
    cudaStreamCreateWithFlags(&st[0], cudaStreamNonBlocking);
    cudaStreamCreateWithFlags(&st[1], cudaStreamNonBlocking);
    cudaEventCreateWithFlags(&ev_root, cudaEventDisableTiming);
    cudaEventCreateWithFlags(&ev_d0, cudaEventDisableTiming);
    cudaEventCreateWithFlags(&ev_d1, cudaEventDisableTiming);
    cudaGetSymbolAddress(&a_counts, g_counts);
    cudaGetSymbolAddress(&a_batchcnt, g_batchcnt);
    cudaGetSymbolAddress(&a_pooled, g_pooled);
  }

  cudaMemsetAsync(a_counts, 0, NN * sizeof(int), 0);
  cudaMemsetAsync(a_batchcnt, 0, BB * sizeof(int), 0);
  cudaMemsetAsync(a_pooled, 0, BB * SS * DD * sizeof(float), 0);
  k_hist<<<(EE + 255) / 256, 256>>>(ei, batch);
  k_scan<<<1, 1024>>>();
  k_scatter<<<(EE + 255) / 256, 256>>>(ei);

  cudaEventRecord(ev_root, 0);
  cudaStreamWaitEvent(st[0], ev_root, 0);
  cudaStreamWaitEvent(st[1], ev_root, 0);

  for (int t = 0; t < SS; t++) {
    int p = t & 1;
    cudaStream_t s = st[p];
    k_gemm1<<<(NN + 63) / 64, 256, 0, s>>>(x_seq + (size_t)t * NN * FF, W1, as1, ad1, p);
    k_gat1<<<(NN * 32 + 255) / 256, 256, 0, s>>>(b1, p);
    k_gemm2<<<(NN + 63) / 64, 256, 0, s>>>(W2, as2, ad2, p);
    k_gat2<<<(NN * 32 + 255) / 256, 256, 0, s>>>(b2, batch, t, p);
  }
  cudaEventRecord(ev_d0, st[0]);
  cudaEventRecord(ev_d1, st[1]);
  cudaStreamWaitEvent(0, ev_d0, 0);
  cudaStreamWaitEvent(0, ev_d1, 0);

  k_final_a<<<96, 192>>>(ipw, ipb);
  k_final_b<<<16, 128>>>(opw, opb, lng, lnb, pw, pb, out);
}

// round 6
// speedup vs baseline: 2.7925x; 1.0525x over previous
#include <cuda_runtime.h>
#include <cuda_fp16.h>
#include <cstdint>

#define NN 20000
#define EE 640000
#define FF 32
#define HH 4
#define CC 64
#define SS 6
#define BB 16
#define DD 64
#define HC 256   // H*C
#define NP 3     // pipeline depth (buffer parity)

// ---------------- device scratch (triple-buffered by timestep mod 3) ----------------
__device__ int    g_counts[NN];
__device__ int    g_rowptr[NN + 1];
__device__ int    g_wpos[NN];
__device__ int    g_col[EE];
__device__ int    g_batchcnt[BB];
__device__ __half g_h1[NP][(size_t)NN * HC];
__device__ __half g_out1[NP][(size_t)NN * HC];
__device__ float4 g_ssrc1[NP][NN];
__device__ float4 g_sdst1[NP][NN];
__device__ __half g_h2[NP][(size_t)NN * CC];
__device__ float  g_ssrc2[NP][NN];
__device__ float  g_sdst2[NP][NN];
__device__ float  g_pooled[BB * SS * DD];
__device__ float  g_sx[96 * 64];
__device__ float  g_qkv[96 * 192];

__device__ __forceinline__ float lrelu(float x) { return x > 0.f ? x : 0.2f * x; }
__device__ __forceinline__ float warpSum(float v) {
#pragma unroll
  for (int o = 16; o; o >>= 1) v += __shfl_xor_sync(0xffffffffu, v, o);
  return v;
}

// ---------------- CSR build ----------------
__global__ void k_hist(const int* __restrict__ ei, const int* __restrict__ batch) {
  int i = blockIdx.x * blockDim.x + threadIdx.x;
  if (i < EE) atomicAdd(&g_counts[ei[EE + i]], 1);
  if (i < NN) atomicAdd(&g_batchcnt[batch[i]], 1);
}

__global__ void k_scan() {
  __shared__ int wsum[32];
  __shared__ int carry;
  int tid = threadIdx.x, lane = tid & 31, wid = tid >> 5;
  if (tid == 0) carry = 0;
  __syncthreads();
  for (int base = 0; base < NN; base += 1024) {
    int i = base + tid;
    int v = (i < NN) ? g_counts[i] : 0;
    int incl = v;
#pragma unroll
    for (int o = 1; o < 32; o <<= 1) { int u = __shfl_up_sync(0xffffffffu, incl, o); if (lane >= o) incl += u; }
    if (lane == 31) wsum[wid] = incl;
    __syncthreads();
    if (wid == 0) {
      int ws = wsum[lane];
      int wi = ws;
#pragma unroll
      for (int o = 1; o < 32; o <<= 1) { int u = __shfl_up_sync(0xffffffffu, wi, o); if (lane >= o) wi += u; }
      wsum[lane] = wi - ws;
    }
    __syncthreads();
    int excl = incl - v + wsum[wid] + carry;
    if (i < NN) { g_rowptr[i] = excl; g_wpos[i] = excl; }
    __syncthreads();
    if (tid == 1023) carry = excl + v;
    __syncthreads();
  }
  if (threadIdx.x == 0) g_rowptr[NN] = carry;
}

__global__ void k_scatter(const int* __restrict__ ei) {
  int i = blockIdx.x * blockDim.x + threadIdx.x;
  if (i >= EE) return;
  int d = ei[EE + i];
  int p = atomicAdd(&g_wpos[d], 1);
  g_col[p] = ei[i];
}

// ---------------- GEMM1: h1 = x @ W1 (fp16 out) ; fused attn scores ----------------
__global__ __launch_bounds__(256) void k_gemm1(const float* __restrict__ x,
                                               const float* __restrict__ W1,
                                               const float* __restrict__ as1,
                                               const float* __restrict__ ad1, int p) {
  __shared__ float Ws[FF * HC];
  __shared__ float Xs[64][33];
  int tid = threadIdx.x;
  for (int i = tid; i < FF * HC / 4; i += 256) ((float4*)Ws)[i] = ((const float4*)W1)[i];
  int m0 = blockIdx.x * 64;
  for (int i = tid; i < 512; i += 256) {
    int r = i >> 3, c4 = i & 7;
    float4 v = make_float4(0.f, 0.f, 0.f, 0.f);
    if (m0 + r < NN) v = ((const float4*)(x + (size_t)(m0 + r) * FF))[c4];
    Xs[r][c4 * 4 + 0] = v.x; Xs[r][c4 * 4 + 1] = v.y;
    Xs[r][c4 * 4 + 2] = v.z; Xs[r][c4 * 4 + 3] = v.w;
  }
  __syncthreads();
  int tx = tid & 31, ty = tid >> 5;
  float acc[8][8] = {};
#pragma unroll
  for (int k = 0; k < FF; k++) {
    float a[8];
#pragma unroll
    for (int i = 0; i < 8; i++) a[i] = Xs[ty * 8 + i][k];
    float4 b0 = *(const float4*)(Ws + k * HC + tx * 8);
    float4 b1v = *(const float4*)(Ws + k * HC + tx * 8 + 4);
    float b[8] = {b0.x, b0.y, b0.z, b0.w, b1v.x, b1v.y, b1v.z, b1v.w};
#pragma unroll
    for (int i = 0; i < 8; i++)
#pragma unroll
      for (int j = 0; j < 8; j++) acc[i][j] += a[i] * b[j];
  }
  float asr[8], adr[8];
#pragma unroll
  for (int j = 0; j < 8; j++) { asr[j] = __ldg(as1 + tx * 8 + j); adr[j] = __ldg(ad1 + tx * 8 + j); }
#pragma unroll
  for (int i = 0; i < 8; i++) {
    int row = m0 + ty * 8 + i;
    float ps = 0.f, pd = 0.f;
#pragma unroll
    for (int j = 0; j < 8; j++) { ps += acc[i][j] * asr[j]; pd += acc[i][j] * adr[j]; }
#pragma unroll
    for (int o = 4; o; o >>= 1) {
      ps += __shfl_down_sync(0xffffffffu, ps, o, 8);
      pd += __shfl_down_sync(0xffffffffu, pd, o, 8);
    }
    if (row < NN) {
      if ((tx & 7) == 0) {
        ((float*)&g_ssrc1[p][row])[tx >> 3] = ps;
        ((float*)&g_sdst1[p][row])[tx >> 3] = pd;
      }
      uint4 u;
      ((__half2*)&u)[0] = __floats2half2_rn(acc[i][0], acc[i][1]);
      ((__half2*)&u)[1] = __floats2half2_rn(acc[i][2], acc[i][3]);
      ((__half2*)&u)[2] = __floats2half2_rn(acc[i][4], acc[i][5]);
      ((__half2*)&u)[3] = __floats2half2_rn(acc[i][6], acc[i][7]);
      ((uint4*)(g_h1[p] + (size_t)row * HC))[tx] = u;
    }
  }
}

// ---------------- GAT1: single-pass softmax-aggregate, warp per dst node ----------------
__global__ __launch_bounds__(256) void k_gat1(const float* __restrict__ b1, int p) {
  __shared__ int    sIdx[8][32];
  __shared__ float4 sE[8][32];
  int wslot = threadIdx.x >> 5;
  int gw = (blockIdx.x * blockDim.x + threadIdx.x) >> 5;
  if (gw >= NN) return;
  int lane = threadIdx.x & 31;
  int base = g_rowptr[gw];
  int deg = g_rowptr[gw + 1] - base;
  float4 sd = g_sdst1[p][gw];
  int head = lane >> 3;
  const __half* h1p = g_h1[p];
  float acc[8] = {0, 0, 0, 0, 0, 0, 0, 0};
  float s0 = 0, s1 = 0, s2 = 0, s3 = 0;

  for (int c0 = 0; c0 <= deg; c0 += 32) {
    int i = c0 + lane;
    float4 e4 = {0, 0, 0, 0};
    int s = gw;
    if (i <= deg) {
      s = (i < deg) ? g_col[base + i] : gw;
      float4 ss = g_ssrc1[p][s];
      e4.x = __expf(lrelu(ss.x + sd.x));
      e4.y = __expf(lrelu(ss.y + sd.y));
      e4.z = __expf(lrelu(ss.z + sd.z));
      e4.w = __expf(lrelu(ss.w + sd.w));
      s0 += e4.x; s1 += e4.y; s2 += e4.z; s3 += e4.w;
    }
    sIdx[wslot][lane] = s;
    sE[wslot][lane] = e4;
    __syncwarp();
    int cnt = min(32, deg + 1 - c0);
#pragma unroll 4
    for (int j = 0; j < cnt; j++) {
      int sj = sIdx[wslot][j];
      float w = ((const float*)&sE[wslot][j])[head];
      uint4 raw = ((const uint4*)(h1p + (size_t)sj * HC))[lane];
      const __half2* ph = (const __half2*)&raw;
      float2 f0 = __half22float2(ph[0]);
      float2 f1 = __half22float2(ph[1]);
      float2 f2 = __half22float2(ph[2]);
      float2 f3 = __half22float2(ph[3]);
      acc[0] += w * f0.x; acc[1] += w * f0.y;
      acc[2] += w * f1.x; acc[3] += w * f1.y;
      acc[4] += w * f2.x; acc[5] += w * f2.y;
      acc[6] += w * f3.x; acc[7] += w * f3.y;
    }
    __syncwarp();
  }
  s0 = warpSum(s0); s1 = warpSum(s1); s2 = warpSum(s2); s3 = warpSum(s3);
  float sums[4] = {s0, s1, s2, s3};
  float inv = 1.f / sums[head];
  float4 bb0 = *(const float4*)(b1 + lane * 8);
  float4 bb1 = *(const float4*)(b1 + lane * 8 + 4);
  float bbs[8] = {bb0.x, bb0.y, bb0.z, bb0.w, bb1.x, bb1.y, bb1.z, bb1.w};
  uint4 u;
  float o[8];
#pragma unroll
  for (int j = 0; j < 8; j++) o[j] = fmaxf(acc[j] * inv + bbs[j], 0.f);
  ((__half2*)&u)[0] = __floats2half2_rn(o[0], o[1]);
  ((__half2*)&u)[1] = __floats2half2_rn(o[2], o[3]);
  ((__half2*)&u)[2] = __floats2half2_rn(o[4], o[5]);
  ((__half2*)&u)[3] = __floats2half2_rn(o[6], o[7]);
  ((uint4*)(g_out1[p] + (size_t)gw * HC))[lane] = u;
}

// ---------------- GEMM2: h2 = out1(fp16) @ W2 ; fused GAT2 scores ----------------
__global__ __launch_bounds__(256) void k_gemm2(const float* __restrict__ W2,
                                               const float* __restrict__ as2,
                                               const float* __restrict__ ad2, int p) {
  __shared__ float As[64][33];
  __shared__ float Bs[32][64];
  int tid = threadIdx.x;
  int tx = tid & 15, ty = tid >> 4;
  int m0 = blockIdx.x * 64;
  float acc[4][4] = {};
  const __half* o1p = g_out1[p];
  for (int k0 = 0; k0 < HC; k0 += 32) {
    for (int i = tid; i < 64 * 16; i += 256) {
      int r = i >> 4, c2 = i & 15;
      int row = m0 + r;
      float2 v = {0.f, 0.f};
      if (row < NN) v = __half22float2(((const __half2*)(o1p + (size_t)row * HC + k0))[c2]);
      As[r][c2 * 2] = v.x;
      As[r][c2 * 2 + 1] = v.y;
    }
    for (int i = tid; i < 32 * 64; i += 256) {
      int r = i >> 6, c = i & 63;
      Bs[r][c] = W2[(k0 + r) * 64 + c];
    }
    __syncthreads();
#pragma unroll
    for (int k = 0; k < 32; k++) {
      float a[4], b[4];
#pragma unroll
      for (int i = 0; i < 4; i++) a[i] = As[ty * 4 + i][k];
#pragma unroll
      for (int j = 0; j < 4; j++) b[j] = Bs[k][tx * 4 + j];
#pragma unroll
      for (int i = 0; i < 4; i++)
#pragma unroll
        for (int j = 0; j < 4; j++) acc[i][j] += a[i] * b[j];
    }
    __syncthreads();
  }
  float asr[4], adr[4];
#pragma unroll
  for (int j = 0; j < 4; j++) { asr[j] = __ldg(as2 + tx * 4 + j); adr[j] = __ldg(ad2 + tx * 4 + j); }
#pragma unroll
  for (int i = 0; i < 4; i++) {
    int row = m0 + ty * 4 + i;
    float ps = 0.f, pd = 0.f;
#pragma unroll
    for (int j = 0; j < 4; j++) { ps += acc[i][j] * asr[j]; pd += acc[i][j] * adr[j]; }
#pragma unroll
    for (int o = 8; o; o >>= 1) {
      ps += __shfl_down_sync(0xffffffffu, ps, o, 16);
      pd += __shfl_down_sync(0xffffffffu, pd, o, 16);
    }
    if (row < NN) {
      if (tx == 0) { g_ssrc2[p][row] = ps; g_sdst2[p][row] = pd; }
      uint2 u;
      ((__half2*)&u)[0] = __floats2half2_rn(acc[i][0], acc[i][1]);
      ((__half2*)&u)[1] = __floats2half2_rn(acc[i][2], acc[i][3]);
      ((uint2*)(g_h2[p] + (size_t)row * 64))[tx] = u;
    }
  }
}

// ---------------- GAT2: single-pass aggregate + mean-pool scatter ----------------
__global__ __launch_bounds__(256) void k_gat2(const float* __restrict__ b2,
                                              const int* __restrict__ batch, int t, int p) {
  __shared__ int   sIdx[8][32];
  __shared__ float sEs[8][32];
  int wslot = threadIdx.x >> 5;
  int gw = (blockIdx.x * blockDim.x + threadIdx.x) >> 5;
  if (gw >= NN) return;
  int lane = threadIdx.x & 31;
  int base = g_rowptr[gw];
  int deg = g_rowptr[gw + 1] - base;
  float sd = g_sdst2[p][gw];
  const __half* h2p = g_h2[p];
  const float* ss2 = g_ssrc2[p];
  float2 acc = {0, 0};
  float sum = 0.f;

  for (int c0 = 0; c0 <= deg; c0 += 32) {
    int i = c0 + lane;
    float e = 0.f;
    int s = gw;
    if (i <= deg) {
      s = (i < deg) ? g_col[base + i] : gw;
      e = __expf(lrelu(ss2[s] + sd));
      sum += e;
    }
    sIdx[wslot][lane] = s;
    sEs[wslot][lane] = e;
    __syncwarp();
    int cnt = min(32, deg + 1 - c0);
#pragma unroll 4
    for (int j = 0; j < cnt; j++) {
      int sj = sIdx[wslot][j];
      float ej = sEs[wslot][j];
      float2 v = __half22float2(((const __half2*)(h2p + (size_t)sj * 64))[lane]);
      acc.x += ej * v.x;
      acc.y += ej * v.y;
    }
    __syncwarp();
  }
  sum = warpSum(sum);
  float inv = 1.f / sum;
  int b = batch[gw];
  float v0 = acc.x * inv + b2[lane * 2];
  float v1 = acc.y * inv + b2[lane * 2 + 1];
  atomicAdd(&g_pooled[b * (SS * DD) + t * DD + lane * 2], v0);
  atomicAdd(&g_pooled[b * (SS * DD) + t * DD + lane * 2 + 1], v1);
}

// ---------------- final A: mean-pool normalize + qkv projection (96 blocks) ----------------
__global__ __launch_bounds__(192) void k_final_a(const float* __restrict__ ipw,
                                                 const float* __restrict__ ipb) {
  __shared__ float xr[64];
  int r = blockIdx.x;
  int tid = threadIdx.x;
  if (tid < 64) {
    int c = g_batchcnt[r / 6];
    float inv = 1.f / (c > 0 ? (float)c : 1.f);
    float v = g_pooled[r * 64 + tid] * inv;
    xr[tid] = v;
    g_sx[r * 64 + tid] = v;
  }
  __syncthreads();
  float acc = ipb[tid];
  const float* wr = &ipw[tid * 64];
#pragma unroll 8
  for (int c = 0; c < 64; c++) acc += xr[c] * wr[c];
  g_qkv[r * 192 + tid] = acc;
}

// ---------------- final B: attention + out_proj + LN + temporal mean + proj (16 blocks) ----------------
__global__ __launch_bounds__(128) void k_final_b(const float* __restrict__ opw, const float* __restrict__ opb,
                                                 const float* __restrict__ lng, const float* __restrict__ lnb,
                                                 const float* __restrict__ pw,  const float* __restrict__ pb,
                                                 float* __restrict__ out) {
  __shared__ float q[6 * 192];
  __shared__ float att[6 * 64];
  __shared__ float ym[6 * 64];
  __shared__ float zacc[64];
  int b = blockIdx.x;
  int tid = threadIdx.x;
  for (int i = tid; i < 6 * 192; i += 128) q[i] = g_qkv[b * 6 * 192 + i];
  if (tid < 64) zacc[tid] = 0.f;
  __syncthreads();
  if (tid < 24) {
    int s1 = tid >> 2, h = tid & 3;
    float sc[6];
    float mx = -1e30f;
    const float* qr = &q[s1 * 192 + h * 16];
    for (int s2 = 0; s2 < 6; s2++) {
      const float* kr = &q[s2 * 192 + 64 + h * 16];
      float d = 0.f;
#pragma unroll
      for (int u = 0; u < 16; u++) d += qr[u] * kr[u];
      sc[s2] = d * 0.25f;
      mx = fmaxf(mx, sc[s2]);
    }
    float ssum = 0.f;
    for (int s2 = 0; s2 < 6; s2++) { sc[s2] = __expf(sc[s2] - mx); ssum += sc[s2]; }
    float invs = 1.f / ssum;
    float o[16];
#pragma unroll
    for (int u = 0; u < 16; u++) o[u] = 0.f;
    for (int s2 = 0; s2 < 6; s2++) {
      float w = sc[s2] * invs;
      const float* vr = &q[s2 * 192 + 128 + h * 16];
#pragma unroll
      for (int u = 0; u < 16; u++) o[u] += w * vr[u];
    }
    for (int u = 0; u < 16; u++) att[s1 * 64 + h * 16 + u] = o[u];
  }
  __syncthreads();
  for (int i = tid; i < 6 * 64; i += 128) {
    int r = i >> 6, c = i & 63;
    float acc = opb[c];
    const float* ar = &att[r * 64];
    const float* wr = &opw[c * 64];
#pragma unroll 8
    for (int k = 0; k < 64; k++) acc += ar[k] * wr[k];
    ym[i] = acc + g_sx[(b * 6 + r) * 64 + c];
  }
  __syncthreads();
  int wid = tid >> 5, lane = tid & 31;
  for (int row = wid; row < 6; row += 4) {
    float y0 = ym[row * 64 + lane];
    float y1 = ym[row * 64 + 32 + lane];
    float s = warpSum(y0 + y1);
    float mu = s * (1.f / 64.f);
    float d0 = y0 - mu, d1 = y1 - mu;
    float vs = warpSum(d0 * d0 + d1 * d1);
    float var = vs * (1.f / 64.f);
    float r = rsqrtf(var + 1e-5f);
    float z0 = d0 * r * lng[lane] + lnb[lane];
    float z1 = d1 * r * lng[lane + 32] + lnb[lane + 32];
    atomicAdd(&zacc[lane], z0 * (1.f / 6.f));
    atomicAdd(&zacc[lane + 32], z1 * (1.f / 6.f));
  }
  __syncthreads();
  if (tid < 64) {
    float acc = pb[tid];
    const float* wr = &pw[tid * 64];
#pragma unroll 8
    for (int k = 0; k < 64; k++) acc += zacc[k] * wr[k];
    out[b * 64 + tid] = acc;
  }
}

// ---------------- launch ----------------
extern "C" void kernel_launch(void* const* d_in, const int* in_sizes, int n_in,
                              void* d_out, int out_size) {
  const float* x_seq = (const float*)d_in[0];
  const int*   ei    = (const int*)d_in[1];
  const int*   batch = (const int*)d_in[2];
  const float* W1    = (const float*)d_in[3];
  const float* as1   = (const float*)d_in[4];
  const float* ad1   = (const float*)d_in[5];
  const float* b1    = (const float*)d_in[6];
  const float* W2    = (const float*)d_in[7];
  const float* as2   = (const float*)d_in[8];
  const float* ad2   = (const float*)d_in[9];
  const float* b2    = (const float*)d_in[10];
  const float* ipw   = (const float*)d_in[11];
  const float* ipb   = (const float*)d_in[12];
  const float* opw   = (const float*)d_in[13];
  const float* opb   = (const float*)d_in[14];
  const float* lng   = (const float*)d_in[15];
  const float* lnb   = (const float*)d_in[16];
  const float* pw    = (const float*)d_in[17];
  const float* pb    = (const float*)d_in[18];
  float* out = (float*)d_out;

  // One-time handles (created on the uncaptured correctness call; reused during capture).
  static bool inited = false;
  static cudaStream_t st[NP];
  static cudaEvent_t ev_root, ev_csr;
  static cudaEvent_t ev_done[NP];
  static void *a_counts, *a_batchcnt, *a_pooled;
  if (!inited) {
    for (int i = 0; i < NP; i++) {
      cudaStreamCreateWithFlags(&st[i], cudaStreamNonBlocking);
      cudaEventCreateWithFlags(&ev_done[i], cudaEventDisableTiming);
    }
    cudaEventCreateWithFlags(&ev_root, cudaEventDisableTiming);
    cudaEventCreateWithFlags(&ev_csr, cudaEventDisableTiming);
    cudaGetSymbolAddress(&a_counts, g_counts);
    cudaGetSymbolAddress(&a_batchcnt, g_batchcnt);
    cudaGetSymbolAddress(&a_pooled, g_pooled);
    inited = true;
  }

  // Fork worker streams off the capture stream.
  cudaEventRecord(ev_root, 0);
  for (int i = 0; i < NP; i++) cudaStreamWaitEvent(st[i], ev_root, 0);

  // CSR build on the capture (legacy) stream — overlaps with gemm1s on workers.
  cudaMemsetAsync(a_counts, 0, NN * sizeof(int), 0);
  cudaMemsetAsync(a_batchcnt, 0, BB * sizeof(int), 0);
  cudaMemsetAsync(a_pooled, 0, BB * SS * DD * sizeof(float), 0);
  k_hist<<<(EE + 255) / 256, 256>>>(ei, batch);
  k_scan<<<1, 1024>>>();
  k_scatter<<<(EE + 255) / 256, 256>>>(ei);
  cudaEventRecord(ev_csr, 0);

  for (int t = 0; t < SS; t++) {
    int p = t % NP;
    cudaStream_t s = st[p];
    // gemm1 depends only on inputs — runs concurrently with CSR build.
    k_gemm1<<<(NN + 63) / 64, 256, 0, s>>>(x_seq + (size_t)t * NN * FF, W1, as1, ad1, p);
    if (t < NP) cudaStreamWaitEvent(s, ev_csr, 0);  // CSR needed from gat1 onward
    k_gat1<<<(NN * 32 + 255) / 256, 256, 0, s>>>(b1, p);
    k_gemm2<<<(NN + 63) / 64, 256, 0, s>>>(W2, as2, ad2, p);
    k_gat2<<<(NN * 32 + 255) / 256, 256, 0, s>>>(b2, batch, t, p);
  }
  for (int i = 0; i < NP; i++) {
    cudaEventRecord(ev_done[i], st[i]);
    cudaStreamWaitEvent(0, ev_done[i], 0);
  }

  k_final_a<<<96, 192>>>(ipw, ipb);
  k_final_b<<<16, 128>>>(opw, opb, lng, lnb, pw, pb, out);
}